// round 14
// baseline (speedup 1.0000x reference)
#include <cuda_runtime.h>
#include <cuda_fp16.h>
#include <math.h>
#include <stdint.h>

#define N_NODES 65536
#define D       256
#define NS      512
#define HID     256
#define KTOP    10
#define EPSC    1e-8f
#define SCALE_C 0.0625f  /* 256^-0.5 */

// ---------------------------------------------------------------------------
// Scratch
// ---------------------------------------------------------------------------
__device__ __half g_xh  [(size_t)N_NODES * D];
__device__ __half g_xrh [(size_t)N_NODES * D];
__device__ __half g_kkh [(size_t)N_NODES * D];
__device__ __half g_q2h [(size_t)N_NODES * D];
__device__ __half g_ndh [(size_t)N_NODES * D];
__device__ float  g_vv  [(size_t)N_NODES * D];
__device__ float  g_nodes[(size_t)N_NODES * D];
__device__ float  g_part[(size_t)NS * 512 * 24];

__device__ float  g_e    [NS * D];
__device__ __half g_qh   [NS * D];
__device__ __half g_k2h  [NS * D];
__device__ float  g_e2cat[NS * 2 * D];
__device__ float  g_h1   [NS * HID];
__device__ float  g_e2   [NS * D];
__device__ float  g_edg  [NS * D];

__device__ __half g_Wkvqh[3 * D * D];
__device__ __half g_Wc0h [D * D];
__device__ __half g_Wc1h [D * D];
__device__ __half g_Wth  [D * D];
__device__ float  g_bkvq [3 * D];
__device__ float  g_bc01 [D];
__device__ float  g_WqTf [D * D];
__device__ float  g_WkTf [D * D];
__device__ float  g_Wm1T [HID * 2 * D];
__device__ float  g_Wm2T [D * HID];
__device__ float  g_cwT  [D * D];

// ---------------------------------------------------------------------------
// helpers
// ---------------------------------------------------------------------------
__device__ __forceinline__ void mma16n8k16(float& c0, float& c1, float& c2, float& c3,
                                           uint32_t a0, uint32_t a1, uint32_t a2, uint32_t a3,
                                           uint32_t b0, uint32_t b1) {
    asm volatile(
        "mma.sync.aligned.m16n8k16.row.col.f32.f16.f16.f32 "
        "{%0,%1,%2,%3}, {%4,%5,%6,%7}, {%8,%9}, {%0,%1,%2,%3};"
        : "+f"(c0), "+f"(c1), "+f"(c2), "+f"(c3)
        : "r"(a0), "r"(a1), "r"(a2), "r"(a3), "r"(b0), "r"(b1));
}
__device__ __forceinline__ void ldsm_x4(uint32_t& r0, uint32_t& r1, uint32_t& r2, uint32_t& r3,
                                        uint32_t addr) {
    asm volatile("ldmatrix.sync.aligned.m8n8.x4.shared.b16 {%0,%1,%2,%3}, [%4];"
                 : "=r"(r0), "=r"(r1), "=r"(r2), "=r"(r3) : "r"(addr));
}
__device__ __forceinline__ void cp_async16(void* smem_dst, const void* gmem_src) {
    uint32_t d = (uint32_t)__cvta_generic_to_shared(smem_dst);
    asm volatile("cp.async.cg.shared.global [%0], [%1], 16;" :: "r"(d), "l"(gmem_src));
}
__device__ __forceinline__ void cp_commit() { asm volatile("cp.async.commit_group;"); }
__device__ __forceinline__ void cp_wait2()  { asm volatile("cp.async.wait_group 2;"); }
__device__ __forceinline__ void cp_wait0()  { asm volatile("cp.async.wait_group 0;"); }

#define LDH   40
#define HBUF  (128 * LDH)
#define MMA_SMEM_BYTES (6 * HBUF * 2)   /* 3-stage: 3 A + 3 B buffers */

struct FragOff {
    uint32_t a_off[2];
    uint32_t b_off[4];
};
__device__ __forceinline__ FragOff make_frag_off(int wid, int lane) {
    FragOff f;
    int warp_m = wid & 3, warp_n = wid >> 2;
#pragma unroll
    for (int mt = 0; mt < 2; mt++)
        f.a_off[mt] = ((warp_m * 32 + mt * 16 + (lane & 15)) * LDH + (lane >> 4) * 8) * 2;
    int b_row = (lane & 7) + ((lane >> 4) & 1) * 8;
    int b_koff = ((lane >> 3) & 1) * 8;
#pragma unroll
    for (int p = 0; p < 4; p++)
        f.b_off[p] = ((warp_n * 64 + p * 16 + b_row) * LDH + b_koff) * 2;
    return f;
}
#define MMA_COMPUTE_CHUNK(Ab, Bb, fo, acc)                                        \
    _Pragma("unroll")                                                             \
    for (int ks = 0; ks < 32; ks += 16) {                                         \
        uint32_t ra[2][4];                                                        \
        uint32_t rb[4][4];                                                        \
        _Pragma("unroll")                                                         \
        for (int mt = 0; mt < 2; mt++)                                            \
            ldsm_x4(ra[mt][0], ra[mt][1], ra[mt][2], ra[mt][3],                   \
                    (Ab) + (fo).a_off[mt] + ks * 2);                              \
        _Pragma("unroll")                                                         \
        for (int p = 0; p < 4; p++)                                               \
            ldsm_x4(rb[p][0], rb[p][1], rb[p][2], rb[p][3],                       \
                    (Bb) + (fo).b_off[p] + ks * 2);                               \
        _Pragma("unroll")                                                         \
        for (int p = 0; p < 4; p++)                                               \
            _Pragma("unroll")                                                     \
            for (int mt = 0; mt < 2; mt++) {                                      \
                mma16n8k16(acc[mt][2 * p][0], acc[mt][2 * p][1],                  \
                           acc[mt][2 * p][2], acc[mt][2 * p][3],                  \
                           ra[mt][0], ra[mt][1], ra[mt][2], ra[mt][3],            \
                           rb[p][0], rb[p][1]);                                   \
                mma16n8k16(acc[mt][2 * p + 1][0], acc[mt][2 * p + 1][1],          \
                           acc[mt][2 * p + 1][2], acc[mt][2 * p + 1][3],          \
                           ra[mt][0], ra[mt][1], ra[mt][2], ra[mt][3],            \
                           rb[p][2], rb[p][3]);                                   \
            }                                                                     \
    }

// 3-stage pipelined chunk loop (variadic: body may contain commas).
#define PIPE3_LOOP(NCHv, LOADFN, ...)                                             \
    LOADFN(0, 0); cp_commit();                                                    \
    LOADFN(1, 1); cp_commit();                                                    \
    for (int ch = 0; ch < (NCHv); ch++) {                                         \
        if (ch + 2 < (NCHv)) LOADFN(ch + 2, (ch + 2) % 3);                        \
        cp_commit();                                                              \
        cp_wait2();                                                               \
        __syncthreads();                                                          \
        { __VA_ARGS__ }                                                           \
        __syncthreads();                                                          \
    }

// ---------------------------------------------------------------------------
// Pipelined fp16 NT GEMM. EPI: 4 = kvq split (only variant still used)
// ---------------------------------------------------------------------------
template <int EPI>
__global__ void __launch_bounds__(256) mma_gemm(
    const __half* __restrict__ A, const __half* __restrict__ B,
    float* __restrict__ C, const float* __restrict__ bias,
    float* __restrict__ Cf2, __half* __restrict__ Ch, __half* __restrict__ Ch2,
    int M, int Ntot, int K) {
    extern __shared__ __half smh[];
    const int tid = threadIdx.x;
    const int wid = tid >> 5, lane = tid & 31;
    const int warp_m = wid & 3;
    const int warp_n = wid >> 2;
    const int bm = blockIdx.y * 128;
    const int bn = blockIdx.x * 128;
    const int grp = lane >> 2;
    const int tig = lane & 3;
    const uint32_t smb = (uint32_t)__cvta_generic_to_shared(smh);
    FragOff fo = make_frag_off(wid, lane);

    float acc[2][8][4];
#pragma unroll
    for (int i = 0; i < 2; i++)
#pragma unroll
        for (int j = 0; j < 8; j++)
#pragma unroll
            for (int r = 0; r < 4; r++) acc[i][j][r] = 0.f;

    const int NCH = K >> 5;
    auto load_tile = [&](int ch, int buf) {
        const __half* Ag = A + (size_t)bm * K + ch * 32;
        const __half* Bg = B + (size_t)bn * K + ch * 32;
        __half* Ad = smh + buf * HBUF;
        __half* Bd = smh + (3 + buf) * HBUF;
#pragma unroll
        for (int i = 0; i < 2; i++) {
            int id = tid + (i << 8);
            int row = id >> 2, c8 = (id & 3) << 3;
            cp_async16(Ad + row * LDH + c8, Ag + (size_t)row * K + c8);
            cp_async16(Bd + row * LDH + c8, Bg + (size_t)row * K + c8);
        }
    };

    PIPE3_LOOP(NCH, load_tile,
        const uint32_t Ab = smb + (ch % 3) * HBUF * 2;
        const uint32_t Bb = smb + (3 + ch % 3) * HBUF * 2;
        MMA_COMPUTE_CHUNK(Ab, Bb, fo, acc);
    )

#pragma unroll
    for (int mt = 0; mt < 2; mt++) {
        int r0 = bm + warp_m * 32 + mt * 16 + grp;
#pragma unroll
        for (int nt = 0; nt < 8; nt++) {
            int c0 = bn + warp_n * 64 + nt * 8 + 2 * tig;
#pragma unroll
            for (int half_ = 0; half_ < 2; half_++) {
                int rr = r0 + half_ * 8;
                float vx = acc[mt][nt][2 * half_ + 0] + bias[c0];
                float vy = acc[mt][nt][2 * half_ + 1] + bias[c0 + 1];
                if constexpr (EPI == 4) {
                    int seg = c0 >> 8;
                    size_t idx = (size_t)rr * D + (c0 & 255);
                    if (seg == 0) {
                        vx = fmaxf(vx, 0.f); vy = fmaxf(vy, 0.f);
                        *reinterpret_cast<__half2*>(Ch + idx) = __floats2half2_rn(vx, vy);
                    } else if (seg == 1) {
                        vx = fmaxf(vx, 0.f); vy = fmaxf(vy, 0.f);
                        float2 o; o.x = vx; o.y = vy;
                        *reinterpret_cast<float2*>(Cf2 + idx) = o;
                    } else {
                        *reinterpret_cast<__half2*>(Ch2 + idx) = __floats2half2_rn(vx, vy);
                    }
                } else {
                    vx = fmaxf(vx, 0.f); vy = fmaxf(vy, 0.f);
                    size_t idx = (size_t)rr * Ntot + c0;
                    float2 o; o.x = vx; o.y = vy;
                    *reinterpret_cast<float2*>(C + idx) = o;
                }
            }
        }
    }
}

// ---------------------------------------------------------------------------
// FUSED tail + out:
// Phase 1: tmp = relu([x|nodes] @ [Wc0;Wc1]^T + bc01 + nodes) -> half SMEM tile
// Phase 2: out = relu(tmp_smem @ Wt^T + bt) -> fp32 global
// One CTA per 128-row block; two 128-col passes per phase.
// SMEM: 6 pipeline buffers (61440B) + tmp tile 128x264 half (67584B) = 129024B
// ---------------------------------------------------------------------------
#define TLD 264   /* half row stride of tmp tile: 528B, 16B aligned */
#define TO_SMEM_BYTES (6 * HBUF * 2 + 128 * TLD * 2)

__global__ void __launch_bounds__(256) tail_out_fused(
    const __half* __restrict__ A1, const __half* __restrict__ A2,
    const __half* __restrict__ B1, const __half* __restrict__ B2,
    const __half* __restrict__ Wt,
    const float* __restrict__ bias01, const float* __restrict__ biasT,
    const float* __restrict__ aux, float* __restrict__ out) {
    extern __shared__ __half smh[];
    __half* tmps = smh + 6 * HBUF;
    const int tid = threadIdx.x;
    const int wid = tid >> 5, lane = tid & 31;
    const int warp_m = wid & 3;
    const int warp_n = wid >> 2;
    const int bm = blockIdx.x * 128;
    const int grp = lane >> 2;
    const int tig = lane & 3;
    const int K = D;
    const uint32_t smb = (uint32_t)__cvta_generic_to_shared(smh);
    const uint32_t tmpb = smb + 6 * HBUF * 2;
    FragOff fo = make_frag_off(wid, lane);

    // A-fragment offsets into the tmp tile (row stride TLD halves)
    uint32_t a2_off[2];
#pragma unroll
    for (int mt = 0; mt < 2; mt++)
        a2_off[mt] = ((warp_m * 32 + mt * 16 + (lane & 15)) * TLD + (lane >> 4) * 8) * 2;

    // ---- Phase 1: tail (K=512 over [A1|A2] / [B1;B2]) ----
    for (int bn2 = 0; bn2 < 2; bn2++) {
        float acc[2][8][4];
#pragma unroll
        for (int i = 0; i < 2; i++)
#pragma unroll
            for (int j = 0; j < 8; j++)
#pragma unroll
                for (int r = 0; r < 4; r++) acc[i][j][r] = 0.f;

        const int bn = bn2 * 128;
        auto load_tile = [&](int ch, int buf) {
            const __half* Ag = (ch < 8) ? A1 + (size_t)bm * K + ch * 32
                                        : A2 + (size_t)bm * K + (ch - 8) * 32;
            const __half* Bg = (ch < 8) ? B1 + (size_t)bn * K + ch * 32
                                        : B2 + (size_t)bn * K + (ch - 8) * 32;
            __half* Ad = smh + buf * HBUF;
            __half* Bd = smh + (3 + buf) * HBUF;
#pragma unroll
            for (int i = 0; i < 2; i++) {
                int id = tid + (i << 8);
                int row = id >> 2, c8 = (id & 3) << 3;
                cp_async16(Ad + row * LDH + c8, Ag + (size_t)row * K + c8);
                cp_async16(Bd + row * LDH + c8, Bg + (size_t)row * K + c8);
            }
        };

        PIPE3_LOOP(16, load_tile,
            const uint32_t Ab = smb + (ch % 3) * HBUF * 2;
            const uint32_t Bb = smb + (3 + ch % 3) * HBUF * 2;
            MMA_COMPUTE_CHUNK(Ab, Bb, fo, acc);
        )

        // epilogue -> tmp tile in SMEM (half)
#pragma unroll
        for (int mt = 0; mt < 2; mt++) {
            int r0 = warp_m * 32 + mt * 16 + grp;
#pragma unroll
            for (int nt = 0; nt < 8; nt++) {
                int c0 = warp_n * 64 + nt * 8 + 2 * tig;
#pragma unroll
                for (int half_ = 0; half_ < 2; half_++) {
                    int rr = r0 + half_ * 8;
                    size_t gidx = (size_t)(bm + rr) * D + bn + c0;
                    float2 aa = *reinterpret_cast<const float2*>(aux + gidx);
                    float vx = fmaxf(acc[mt][nt][2 * half_ + 0] + bias01[bn + c0] + aa.x, 0.f);
                    float vy = fmaxf(acc[mt][nt][2 * half_ + 1] + bias01[bn + c0 + 1] + aa.y, 0.f);
                    *reinterpret_cast<__half2*>(tmps + rr * TLD + bn + c0) =
                        __floats2half2_rn(vx, vy);
                }
            }
        }
        __syncthreads();
    }

    // ---- Phase 2: out = relu(tmp @ Wt^T + bt) ----
    for (int bn2 = 0; bn2 < 2; bn2++) {
        float acc[2][8][4];
#pragma unroll
        for (int i = 0; i < 2; i++)
#pragma unroll
            for (int j = 0; j < 8; j++)
#pragma unroll
                for (int r = 0; r < 4; r++) acc[i][j][r] = 0.f;

        const int bn = bn2 * 128;
        auto load_tile = [&](int ch, int buf) {
            const __half* Bg = Wt + (size_t)bn * K + ch * 32;
            __half* Bd = smh + (3 + buf) * HBUF;
            int row = tid >> 1, c8 = (tid & 1) << 4;
            cp_async16(Bd + row * LDH + c8, Bg + (size_t)row * K + c8);
            cp_async16(Bd + row * LDH + c8 + 8, Bg + (size_t)row * K + c8 + 8);
        };

        PIPE3_LOOP(8, load_tile,
            const uint32_t Ab = tmpb + ch * 64;     /* 32 halves per chunk */
            const uint32_t Bb = smb + (3 + ch % 3) * HBUF * 2;
            _Pragma("unroll")
            for (int ks = 0; ks < 32; ks += 16) {
                uint32_t ra[2][4];
                uint32_t rb[4][4];
                _Pragma("unroll")
                for (int mt = 0; mt < 2; mt++)
                    ldsm_x4(ra[mt][0], ra[mt][1], ra[mt][2], ra[mt][3],
                            Ab + a2_off[mt] + ks * 2);
                _Pragma("unroll")
                for (int p = 0; p < 4; p++)
                    ldsm_x4(rb[p][0], rb[p][1], rb[p][2], rb[p][3],
                            Bb + fo.b_off[p] + ks * 2);
                _Pragma("unroll")
                for (int p = 0; p < 4; p++)
                    _Pragma("unroll")
                    for (int mt = 0; mt < 2; mt++) {
                        mma16n8k16(acc[mt][2 * p][0], acc[mt][2 * p][1],
                                   acc[mt][2 * p][2], acc[mt][2 * p][3],
                                   ra[mt][0], ra[mt][1], ra[mt][2], ra[mt][3],
                                   rb[p][0], rb[p][1]);
                        mma16n8k16(acc[mt][2 * p + 1][0], acc[mt][2 * p + 1][1],
                                   acc[mt][2 * p + 1][2], acc[mt][2 * p + 1][3],
                                   ra[mt][0], ra[mt][1], ra[mt][2], ra[mt][3],
                                   rb[p][2], rb[p][3]);
                    }
            }
        )

#pragma unroll
        for (int mt = 0; mt < 2; mt++) {
            int r0 = bm + warp_m * 32 + mt * 16 + grp;
#pragma unroll
            for (int nt = 0; nt < 8; nt++) {
                int c0 = bn + warp_n * 64 + nt * 8 + 2 * tig;
#pragma unroll
                for (int half_ = 0; half_ < 2; half_++) {
                    int rr = r0 + half_ * 8;
                    float vx = fmaxf(acc[mt][nt][2 * half_ + 0] + biasT[c0], 0.f);
                    float vy = fmaxf(acc[mt][nt][2 * half_ + 1] + biasT[c0 + 1], 0.f);
                    float2 o; o.x = vx; o.y = vy;
                    *reinterpret_cast<float2*>(out + (size_t)rr * D + c0) = o;
                }
            }
        }
        __syncthreads();
    }
}

// ---------------------------------------------------------------------------
// FUSED dots2 + node attention
// ---------------------------------------------------------------------------
#define LGD 133
#define FUS_SMEM_BYTES (128 * LGD * 4 + 128 * KTOP * 4 + 128 * KTOP * 4)

__global__ void __launch_bounds__(256) dots2_node_fused(
    const __half* __restrict__ A, const __half* __restrict__ Bk,
    const float* __restrict__ edg,
    float* __restrict__ nodes, __half* __restrict__ nodesh) {
    extern __shared__ __half smh[];
    float* logits = reinterpret_cast<float*>(smh);
    float* wv_s = logits + 128 * LGD;
    int*   wi_s = reinterpret_cast<int*>(wv_s + 128 * KTOP);

    const int tid = threadIdx.x;
    const int wid = tid >> 5, lane = tid & 31;
    const int warp_m = wid & 3;
    const int warp_n = wid >> 2;
    const int bm = blockIdx.x * 128;
    const int grp = lane >> 2;
    const int tig = lane & 3;
    const int K = D;
    const uint32_t smb = (uint32_t)__cvta_generic_to_shared(smh);
    FragOff fo = make_frag_off(wid, lane);

    float m_run = -INFINITY, z_run = 0.f;
    float tv[KTOP]; int ti[KTOP];
#pragma unroll
    for (int i = 0; i < KTOP; i++) { tv[i] = -INFINITY; ti[i] = 0; }

    for (int sc = 0; sc < 4; sc++) {
        float acc[2][8][4];
#pragma unroll
        for (int i = 0; i < 2; i++)
#pragma unroll
            for (int j = 0; j < 8; j++)
#pragma unroll
                for (int r = 0; r < 4; r++) acc[i][j][r] = 0.f;

        const __half* Bg_base = Bk + (size_t)(sc * 128) * K;
        auto load_tile = [&](int ch, int buf) {
            const __half* Ag = A + (size_t)bm * K + ch * 32;
            const __half* Bg = Bg_base + ch * 32;
            __half* Ad = smh + buf * HBUF;
            __half* Bd = smh + (3 + buf) * HBUF;
#pragma unroll
            for (int i = 0; i < 2; i++) {
                int id = tid + (i << 8);
                int row = id >> 2, c8 = (id & 3) << 3;
                cp_async16(Ad + row * LDH + c8, Ag + (size_t)row * K + c8);
                cp_async16(Bd + row * LDH + c8, Bg + (size_t)row * K + c8);
            }
        };

        PIPE3_LOOP(8, load_tile,
            const uint32_t Ab = smb + (ch % 3) * HBUF * 2;
            const uint32_t Bb = smb + (3 + ch % 3) * HBUF * 2;
            MMA_COMPUTE_CHUNK(Ab, Bb, fo, acc);
        )

#pragma unroll
        for (int mt = 0; mt < 2; mt++) {
            int r0 = warp_m * 32 + mt * 16 + grp;
#pragma unroll
            for (int nt = 0; nt < 8; nt++) {
                int c0 = warp_n * 64 + nt * 8 + 2 * tig;
#pragma unroll
                for (int half_ = 0; half_ < 2; half_++) {
                    int rr = r0 + half_ * 8;
                    logits[rr * LGD + c0]     = acc[mt][nt][2 * half_ + 0] * SCALE_C;
                    logits[rr * LGD + c0 + 1] = acc[mt][nt][2 * half_ + 1] * SCALE_C;
                }
            }
        }
        __syncthreads();
        if (tid < 128) {
            const float* lr = logits + tid * LGD;
            for (int j = 0; j < 128; j++) {
                float v = lr[j];
                if (v > m_run) { z_run *= __expf(m_run - v); m_run = v; }
                z_run += __expf(v - m_run);
                if (v > tv[KTOP - 1]) {
                    int ix = sc * 128 + j;
                    float vt = v;
#pragma unroll
                    for (int p = 0; p < KTOP; p++)
                        if (vt > tv[p]) {
                            float tf = tv[p]; tv[p] = vt; vt = tf;
                            int tt = ti[p]; ti[p] = ix; ix = tt;
                        }
                }
            }
        }
        __syncthreads();
    }
    if (tid < 128) {
        float zin = 1.f / z_run;
#pragma unroll
        for (int i = 0; i < KTOP; i++) {
            wv_s[tid * KTOP + i] = __expf(tv[i] - m_run) * zin;
            wi_s[tid * KTOP + i] = ti[i];
        }
    }
    __syncthreads();
    for (int rr = 0; rr < 16; rr++) {
        int r = wid * 16 + rr;
        float w_[KTOP]; int ix_[KTOP];
#pragma unroll
        for (int i = 0; i < KTOP; i++) { w_[i] = wv_s[r * KTOP + i]; ix_[i] = wi_s[r * KTOP + i]; }
        float* po = nodes + (size_t)(bm + r) * D;
        __half* ph = nodesh + (size_t)(bm + r) * D;
#pragma unroll
        for (int j = 0; j < 8; j++) {
            int c = lane + 32 * j;
            float a2 = 0.f;
#pragma unroll
            for (int i = 0; i < KTOP; i++) a2 += w_[i] * edg[(size_t)ix_[i] * D + c];
            po[c] = a2;
            ph[c] = __float2half_rn(a2);
        }
    }
}

// ---------------------------------------------------------------------------
// dots1 Phase A
// ---------------------------------------------------------------------------
#define FUS1_SMEM_BYTES (128 * LGD * 4)

__global__ void __launch_bounds__(256) dots1_partial(
    const __half* __restrict__ A, const __half* __restrict__ Bk,
    float* __restrict__ part) {
    extern __shared__ __half smh[];
    float* logits = reinterpret_cast<float*>(smh);
    const int tid = threadIdx.x;
    const int wid = tid >> 5, lane = tid & 31;
    const int warp_m = wid & 3;
    const int warp_n = wid >> 2;
    const int bm = blockIdx.y * 128;
    const int bnc = blockIdx.x;
    const int grp = lane >> 2;
    const int tig = lane & 3;
    const int K = D;
    const uint32_t smb = (uint32_t)__cvta_generic_to_shared(smh);
    FragOff fo = make_frag_off(wid, lane);

    float acc[2][8][4];
#pragma unroll
    for (int i = 0; i < 2; i++)
#pragma unroll
        for (int j = 0; j < 8; j++)
#pragma unroll
            for (int r = 0; r < 4; r++) acc[i][j][r] = 0.f;

    const __half* Bg_base = Bk + (size_t)bnc * 128 * K;
    auto load_tile = [&](int ch, int buf) {
        const __half* Ag = A + (size_t)bm * K + ch * 32;
        const __half* Bg = Bg_base + ch * 32;
        __half* Ad = smh + buf * HBUF;
        __half* Bd = smh + (3 + buf) * HBUF;
#pragma unroll
        for (int i = 0; i < 2; i++) {
            int id = tid + (i << 8);
            int row = id >> 2, c8 = (id & 3) << 3;
            cp_async16(Ad + row * LDH + c8, Ag + (size_t)row * K + c8);
            cp_async16(Bd + row * LDH + c8, Bg + (size_t)row * K + c8);
        }
    };

    PIPE3_LOOP(8, load_tile,
        const uint32_t Ab = smb + (ch % 3) * HBUF * 2;
        const uint32_t Bb = smb + (3 + ch % 3) * HBUF * 2;
        MMA_COMPUTE_CHUNK(Ab, Bb, fo, acc);
    )

#pragma unroll
    for (int mt = 0; mt < 2; mt++) {
        int r0 = warp_m * 32 + mt * 16 + grp;
#pragma unroll
        for (int nt = 0; nt < 8; nt++) {
            int c0 = warp_n * 64 + nt * 8 + 2 * tig;
#pragma unroll
            for (int half_ = 0; half_ < 2; half_++) {
                int rr = r0 + half_ * 8;
                logits[rr * LGD + c0]     = acc[mt][nt][2 * half_ + 0] * SCALE_C;
                logits[rr * LGD + c0 + 1] = acc[mt][nt][2 * half_ + 1] * SCALE_C;
            }
        }
    }
    __syncthreads();
    if (tid < 128) {
        const float* lr = logits + tid * LGD;
        float m = -INFINITY, z = 0.f;
        float tv[KTOP]; int ti[KTOP];
#pragma unroll
        for (int i = 0; i < KTOP; i++) { tv[i] = -INFINITY; ti[i] = 0; }
        for (int j = 0; j < 128; j++) {
            float v = lr[j];
            if (v > m) { z *= __expf(m - v); m = v; }
            z += __expf(v - m);
            if (v > tv[KTOP - 1]) {
                int ix = bnc * 128 + j;
                float vt = v;
#pragma unroll
                for (int p = 0; p < KTOP; p++)
                    if (vt > tv[p]) {
                        float tf = tv[p]; tv[p] = vt; vt = tf;
                        int tt = ti[p]; ti[p] = ix; ix = tt;
                    }
            }
        }
        float* rec = part + ((size_t)(bm + tid) * 512 + bnc) * 24;
        rec[0] = m; rec[1] = z;
#pragma unroll
        for (int i = 0; i < KTOP; i++) {
            rec[2 + i] = tv[i];
            rec[12 + i] = __int_as_float(ti[i]);
        }
    }
}

// ---------------------------------------------------------------------------
// dots1 Phase B merge
// ---------------------------------------------------------------------------
__global__ void slot_merge(const float* __restrict__ part, const float* __restrict__ vv,
                           const float* __restrict__ e, float* __restrict__ e2cat) {
    __shared__ float sv[256 * KTOP];
    __shared__ int   si[256 * KTOP];
    __shared__ float sm_m[256];
    __shared__ float sm_z[256];
    __shared__ float sw[KTOP];
    __shared__ int   sx[KTOP];
    int s = blockIdx.x, tid = threadIdx.x;

    const float* r0 = part + ((size_t)s * 512 + 2 * tid) * 24;
    const float* r1 = r0 + 24;
    float m = r0[0], z = r0[1];
    float tv[KTOP]; int ti[KTOP];
#pragma unroll
    for (int i = 0; i < KTOP; i++) { tv[i] = r0[2 + i]; ti[i] = __float_as_int(r0[12 + i]); }
    {
        float mb = r1[0], zb = r1[1];
        float mn = fmaxf(m, mb);
        z = z * __expf(m - mn) + zb * __expf(mb - mn);
        m = mn;
#pragma unroll
        for (int i = 0; i < KTOP; i++) {
            float v = r1[2 + i];
            int ix = __float_as_int(r1[12 + i]);
            if (v > tv[KTOP - 1]) {
#pragma unroll
                for (int p = 0; p < KTOP; p++)
                    if (v > tv[p]) {
                        float tf = tv[p]; tv[p] = v; v = tf;
                        int tt = ti[p]; ti[p] = ix; ix = tt;
                    }
            }
        }
    }
#pragma unroll
    for (int i = 0; i < KTOP; i++) { sv[tid * KTOP + i] = tv[i]; si[tid * KTOP + i] = ti[i]; }
    sm_m[tid] = m; sm_z[tid] = z;
    __syncthreads();
    for (int stride = 128; stride >= 1; stride >>= 1) {
        if (tid < stride) {
#pragma unroll
            for (int i = 0; i < KTOP; i++) { tv[i] = sv[tid * KTOP + i]; ti[i] = si[tid * KTOP + i]; }
#pragma unroll
            for (int i = 0; i < KTOP; i++) {
                float v = sv[(tid + stride) * KTOP + i];
                int ix = si[(tid + stride) * KTOP + i];
                if (v > tv[KTOP - 1]) {
#pragma unroll
                    for (int p = 0; p < KTOP; p++)
                        if (v > tv[p]) {
                            float tf = tv[p]; tv[p] = v; v = tf;
                            int tt = ti[p]; ti[p] = ix; ix = tt;
                        }
                }
            }
#pragma unroll
            for (int i = 0; i < KTOP; i++) { sv[tid * KTOP + i] = tv[i]; si[tid * KTOP + i] = ti[i]; }
            float ma = sm_m[tid], za = sm_z[tid];
            float mb = sm_m[tid + stride], zb = sm_z[tid + stride];
            float mn = fmaxf(ma, mb);
            float zn = za * __expf(ma - mn) + zb * __expf(mb - mn);
            sm_m[tid] = mn; sm_z[tid] = zn;
        }
        __syncthreads();
    }
    float maxv = sm_m[0];
    float Z = sm_z[0];
    if (tid < KTOP) {
        float p = __expf(sv[tid] - maxv) / Z;
        sw[tid] = (p + EPSC) / (1.f + (float)N_NODES * EPSC);
        sx[tid] = si[tid];
    }
    __syncthreads();
    float acc = 0.f;
#pragma unroll
    for (int i = 0; i < KTOP; i++) acc += sw[i] * vv[(size_t)sx[i] * D + tid];
    e2cat[(size_t)s * 2 * D + D + tid] = acc;
    e2cat[(size_t)s * 2 * D + tid] = e[(size_t)s * D + tid];
}

// ---------------------------------------------------------------------------
// prep: weight transposes + bias tasks + edges LN. grid (64, 14), block (32,8)
// ---------------------------------------------------------------------------
__device__ __forceinline__ void tr_tile(const float* in, float* outF, __half* outH,
                                        int R, int C, int bx, float (*tile)[33]) {
    int tx = threadIdx.x, tyw = threadIdx.y;
    int xt = bx & (C / 32 - 1), yt = bx / (C / 32);
    int bxc = xt * 32, byr = yt * 32;
    for (int y = tyw; y < 32; y += 8)
        tile[y][tx] = in[(size_t)(byr + y) * C + bxc + tx];
    __syncthreads();
    if (outH) {
        for (int y = tyw; y < 32; y += 8)
            outH[(size_t)(bxc + y) * R + byr + tx] = __float2half_rn(tile[tx][y]);
    } else {
        for (int y = tyw; y < 32; y += 8)
            outF[(size_t)(bxc + y) * R + byr + tx] = tile[tx][y];
    }
}

__global__ void prep(
    const float* Wk, const float* Wv, const float* Wq, const float* Wc0,
    const float* Wc1, const float* Wt, const float* cw, const float* Wm1,
    const float* Wm2,
    __half* Wkvqh, __half* Wc0h, __half* Wc1h, __half* Wth,
    float* WqTf, float* WkTf, float* cwT, float* Wm1T, float* Wm2T,
    const float* bk, const float* bv, const float* bq, float* bkvq,
    const float* bc0, const float* bc1, float* bc01,
    const float* noise, const float* emu, const float* elog,
    const float* lew, const float* leb, float* e) {
    __shared__ float tile[32][33];
    int task = blockIdx.y, bx = blockIdx.x;
    switch (task) {
    case 0: tr_tile(Wk,  nullptr, Wkvqh,             D, D, bx, tile); break;
    case 1: tr_tile(Wv,  nullptr, Wkvqh + D * D,     D, D, bx, tile); break;
    case 2: tr_tile(Wq,  nullptr, Wkvqh + 2 * D * D, D, D, bx, tile); break;
    case 3: tr_tile(Wc0, nullptr, Wc0h, D, D, bx, tile); break;
    case 4: tr_tile(Wc1, nullptr, Wc1h, D, D, bx, tile); break;
    case 5: tr_tile(Wt,  nullptr, Wth,  D, D, bx, tile); break;
    case 6: tr_tile(Wq,  WqTf, nullptr, D, D, bx, tile); break;
    case 7: tr_tile(Wk,  WkTf, nullptr, D, D, bx, tile); break;
    case 8: tr_tile(cw,  cwT,  nullptr, D, D, bx, tile); break;
    case 9: tr_tile(Wm2, Wm2T, nullptr, HID, D, bx, tile); break;
    case 10: tr_tile(Wm1, Wm1T, nullptr, 2 * D, HID, bx, tile); break;
    case 11: tr_tile(Wm1, Wm1T, nullptr, 2 * D, HID, bx + 64, tile); break;
    case 12: {
        if (bx == 0) {
            int i = threadIdx.y * 32 + threadIdx.x;
            bkvq[i] = bk[i]; bkvq[D + i] = bv[i]; bkvq[2 * D + i] = bq[i];
            bc01[i] = bc0[i] + bc1[i];
        }
        break;
    }
    default: {  // 13: edges LN
        int warp = bx * 8 + threadIdx.y;
        int lane = threadIdx.x;
        const float* r = noise + (size_t)warp * D;
        float v[8]; float s = 0.f;
#pragma unroll
        for (int j = 0; j < 8; j++) {
            int c = lane + 32 * j;
            v[j] = emu[c] + expf(elog[c]) * r[c];
            s += v[j];
        }
#pragma unroll
        for (int st = 16; st; st >>= 1) s += __shfl_xor_sync(0xffffffffu, s, st);
        float mu = s * (1.f / 256.f);
        float q = 0.f;
#pragma unroll
        for (int j = 0; j < 8; j++) { float d2 = v[j] - mu; q += d2 * d2; }
#pragma unroll
        for (int st = 16; st; st >>= 1) q += __shfl_xor_sync(0xffffffffu, q, st);
        float rinv = rsqrtf(q * (1.f / 256.f) + 1e-5f);
        float* po = e + (size_t)warp * D;
#pragma unroll
        for (int j = 0; j < 8; j++) {
            int c = lane + 32 * j;
            po[c] = (v[j] - mu) * rinv * lew[c] + leb[c];
        }
        break;
    }
    }
}

// ---------------------------------------------------------------------------
// LayerNorm -> half + x->half copy
// ---------------------------------------------------------------------------
__global__ void ln_rows(const float* __restrict__ x, const float* __restrict__ w,
                        const float* __restrict__ b, __half* __restrict__ o,
                        __half* __restrict__ xrh, int M) {
    int warp = (blockIdx.x * blockDim.x + threadIdx.x) >> 5;
    int lane = threadIdx.x & 31;
    if (warp >= M) return;
    const float* r = x + (size_t)warp * D;
    float v[8]; float s = 0.f;
#pragma unroll
    for (int j = 0; j < 8; j++) { v[j] = r[lane + 32 * j]; s += v[j]; }
#pragma unroll
    for (int st = 16; st; st >>= 1) s += __shfl_xor_sync(0xffffffffu, s, st);
    float mu = s * (1.f / 256.f);
    float q = 0.f;
#pragma unroll
    for (int j = 0; j < 8; j++) { float d = v[j] - mu; q += d * d; }
#pragma unroll
    for (int st = 16; st; st >>= 1) q += __shfl_xor_sync(0xffffffffu, q, st);
    float rinv = rsqrtf(q * (1.f / 256.f) + 1e-5f);
    __half* po = o + (size_t)warp * D;
    __half* px = xrh + (size_t)warp * D;
#pragma unroll
    for (int j = 0; j < 8; j++) {
        int c = lane + 32 * j;
        po[c] = __float2half_rn((v[j] - mu) * rinv * w[c] + b[c]);
        px[c] = __float2half_rn(v[j]);
    }
}

// ---------------------------------------------------------------------------
// Small fp32 NT GEMM: 32x32 tile, 128 threads. DUAL variant: second B.
// ---------------------------------------------------------------------------
#define GSW 260
#define GS_SMEM_BYTES  (2 * 32 * GSW * 4)
#define GS_SMEM_BYTES3 (3 * 32 * GSW * 4)

template <bool BIAS, bool RELU, bool OUTH, bool DUAL>
__global__ void __launch_bounds__(128) gemm_small(
    const float* __restrict__ A, const float* __restrict__ B,
    const float* __restrict__ B2d,
    float* __restrict__ C, __half* __restrict__ Ch, float* __restrict__ C2,
    const float* __restrict__ bias, const float* __restrict__ bias2,
    int M, int N, int K) {
    extern __shared__ float gs[];
    float* As = gs;
    float* Bs = gs + 32 * GSW;
    float* B2s = gs + 2 * 32 * GSW;
    const int tid = threadIdx.x;
    const int tx = tid & 7, ty = tid >> 3;
    const int bm = blockIdx.y * 32, bn = blockIdx.x * 32;

    float acc[2][4], acc2[2][4];
#pragma unroll
    for (int i = 0; i < 2; i++)
#pragma unroll
        for (int j = 0; j < 4; j++) { acc[i][j] = 0.f; acc2[i][j] = 0.f; }

    for (int k0 = 0; k0 < K; k0 += 256) {
#pragma unroll
        for (int i = 0; i < 16; i++) {
            int id = tid + i * 128;
            int row = id >> 6, c4 = (id & 63) << 2;
            cp_async16(&As[row * GSW + c4], &A[(size_t)(bm + row) * K + k0 + c4]);
            cp_async16(&Bs[row * GSW + c4], &B[(size_t)(bn + row) * K + k0 + c4]);
            if (DUAL)
                cp_async16(&B2s[row * GSW + c4], &B2d[(size_t)(bn + row) * K + k0 + c4]);
        }
        cp_commit();
        cp_wait0();
        __syncthreads();
#pragma unroll 4
        for (int k = 0; k < 256; k += 4) {
            float4 a0 = *reinterpret_cast<const float4*>(&As[(ty * 2 + 0) * GSW + k]);
            float4 a1 = *reinterpret_cast<const float4*>(&As[(ty * 2 + 1) * GSW + k]);
#pragma unroll
            for (int j = 0; j < 4; j++) {
                float4 b4 = *reinterpret_cast<const float4*>(&Bs[(tx + 8 * j) * GSW + k]);
                acc[0][j] += a0.x * b4.x + a0.y * b4.y + a0.z * b4.z + a0.w * b4.w;
                acc[1][j] += a1.x * b4.x + a1.y * b4.y + a1.z * b4.z + a1.w * b4.w;
                if (DUAL) {
                    float4 c4v = *reinterpret_cast<const float4*>(&B2s[(tx + 8 * j) * GSW + k]);
                    acc2[0][j] += a0.x * c4v.x + a0.y * c4v.y + a0.z * c4v.z + a0.w * c4v.w;
                    acc2[1][j] += a1.x * c4v.x + a1.y * c4v.y + a1.z * c4v.z + a1.w * c4v.w;
                }
            }
        }
        __syncthreads();
    }
#pragma unroll
    for (int i = 0; i < 2; i++) {
        int m = bm + ty * 2 + i;
#pragma unroll
        for (int j = 0; j < 4; j++) {
            int n = bn + tx + 8 * j;
            float v = acc[i][j];
            if (BIAS) v += bias[n];
            if (RELU) v = fmaxf(v, 0.f);
            if (OUTH) Ch[(size_t)m * N + n] = __float2half_rn(v);
            else      C [(size_t)m * N + n] = v;
            if (DUAL) {
                float v2 = acc2[i][j] + bias2[n];
                C2[(size_t)m * N + n] = v2;
            }
        }
    }
}

// ---------------------------------------------------------------------------
// Launch
// ---------------------------------------------------------------------------
extern "C" void kernel_launch(void* const* d_in, const int* in_sizes, int n_in,
                              void* d_out, int out_size) {
    (void)in_sizes; (void)n_in; (void)out_size;
    const float* x      = (const float*)d_in[0];
    const float* enoise = (const float*)d_in[1];
    const float* emu    = (const float*)d_in[2];
    const float* elog   = (const float*)d_in[3];
    const float* lnw    = (const float*)d_in[4];
    const float* lnb    = (const float*)d_in[5];
    const float* lew    = (const float*)d_in[6];
    const float* leb    = (const float*)d_in[7];
    const float* Wq = (const float*)d_in[8];  const float* bq = (const float*)d_in[9];
    const float* Wk = (const float*)d_in[10]; const float* bk = (const float*)d_in[11];
    const float* Wv = (const float*)d_in[12]; const float* bv = (const float*)d_in[13];
    const float* Wm1 = (const float*)d_in[14]; const float* bm1 = (const float*)d_in[15];
    const float* Wm2 = (const float*)d_in[16]; const float* bm2 = (const float*)d_in[17];
    const float* cw = (const float*)d_in[18];  const float* cb = (const float*)d_in[19];
    const float* Wc0 = (const float*)d_in[20]; const float* bc0 = (const float*)d_in[21];
    const float* Wc1 = (const float*)d_in[22]; const float* bc1 = (const float*)d_in[23];
    const float* Wt = (const float*)d_in[24];  const float* bt = (const float*)d_in[25];
    float* out = (float*)d_out;

    void* p;
    cudaGetSymbolAddress(&p, g_xh);    __half* xh = (__half*)p;
    cudaGetSymbolAddress(&p, g_xrh);   __half* xrh = (__half*)p;
    cudaGetSymbolAddress(&p, g_kkh);   __half* kkh = (__half*)p;
    cudaGetSymbolAddress(&p, g_q2h);   __half* q2h = (__half*)p;
    cudaGetSymbolAddress(&p, g_ndh);   __half* ndh = (__half*)p;
    cudaGetSymbolAddress(&p, g_vv);    float* vvb = (float*)p;
    cudaGetSymbolAddress(&p, g_nodes); float* nodesb = (float*)p;
    cudaGetSymbolAddress(&p, g_part);  float* part = (float*)p;
    cudaGetSymbolAddress(&p, g_e);     float* e = (float*)p;
    cudaGetSymbolAddress(&p, g_qh);    __half* qh = (__half*)p;
    cudaGetSymbolAddress(&p, g_k2h);   __half* k2h = (__half*)p;
    cudaGetSymbolAddress(&p, g_e2cat); float* e2cat = (float*)p;
    cudaGetSymbolAddress(&p, g_h1);    float* h1 = (float*)p;
    cudaGetSymbolAddress(&p, g_e2);    float* e2 = (float*)p;
    cudaGetSymbolAddress(&p, g_edg);   float* edg = (float*)p;
    cudaGetSymbolAddress(&p, g_Wkvqh); __half* Wkvqh = (__half*)p;
    cudaGetSymbolAddress(&p, g_Wc0h);  __half* Wc0h = (__half*)p;
    cudaGetSymbolAddress(&p, g_Wc1h);  __half* Wc1h = (__half*)p;
    cudaGetSymbolAddress(&p, g_Wth);   __half* Wth = (__half*)p;
    cudaGetSymbolAddress(&p, g_bkvq);  float* bkvq = (float*)p;
    cudaGetSymbolAddress(&p, g_bc01);  float* bc01 = (float*)p;
    cudaGetSymbolAddress(&p, g_WqTf);  float* WqTf = (float*)p;
    cudaGetSymbolAddress(&p, g_WkTf);  float* WkTf = (float*)p;
    cudaGetSymbolAddress(&p, g_Wm1T);  float* Wm1T = (float*)p;
    cudaGetSymbolAddress(&p, g_Wm2T);  float* Wm2T = (float*)p;
    cudaGetSymbolAddress(&p, g_cwT);   float* cwT = (float*)p;

    cudaFuncSetAttribute(mma_gemm<4>, cudaFuncAttributeMaxDynamicSharedMemorySize, MMA_SMEM_BYTES);
    cudaFuncSetAttribute(tail_out_fused, cudaFuncAttributeMaxDynamicSharedMemorySize, TO_SMEM_BYTES);
    cudaFuncSetAttribute(dots2_node_fused, cudaFuncAttributeMaxDynamicSharedMemorySize, FUS_SMEM_BYTES);
    cudaFuncSetAttribute(dots1_partial, cudaFuncAttributeMaxDynamicSharedMemorySize, FUS1_SMEM_BYTES);
    cudaFuncSetAttribute(gemm_small<true, true, true, false>, cudaFuncAttributeMaxDynamicSharedMemorySize, GS_SMEM_BYTES);
    cudaFuncSetAttribute(gemm_small<true, true, false, false>, cudaFuncAttributeMaxDynamicSharedMemorySize, GS_SMEM_BYTES);
    cudaFuncSetAttribute(gemm_small<true, false, false, false>, cudaFuncAttributeMaxDynamicSharedMemorySize, GS_SMEM_BYTES);
    cudaFuncSetAttribute(gemm_small<true, true, true, true>, cudaFuncAttributeMaxDynamicSharedMemorySize, GS_SMEM_BYTES3);

    prep<<<dim3(64, 14), dim3(32, 8)>>>(
        Wk, Wv, Wq, Wc0, Wc1, Wt, cw, Wm1, Wm2,
        Wkvqh, Wc0h, Wc1h, Wth, WqTf, WkTf, cwT, Wm1T, Wm2T,
        bk, bv, bq, bkvq, bc0, bc1, bc01,
        enoise, emu, elog, lew, leb, e);

    ln_rows<<<N_NODES / 8, 256>>>(x, lnw, lnb, xh, xrh, N_NODES);

    // fused: kk(half,relu), vv(fp32,relu), q2(half)
    mma_gemm<4><<<dim3(6, 512), 256, MMA_SMEM_BYTES>>>(
        xh, Wkvqh, nullptr, bkvq, vvb, kkh, q2h, N_NODES, 3 * D, D);

    // q = relu(e@Wq+bq) -> half
    gemm_small<true, true, true, false><<<dim3(8, 16), 128, GS_SMEM_BYTES>>>(
        e, WqTf, nullptr, nullptr, qh, nullptr, bq, nullptr, NS, D, D);

    // dots1 partials + merge
    dots1_partial<<<dim3(512, 4), 256, FUS1_SMEM_BYTES>>>(qh, kkh, part);
    slot_merge<<<NS, 256>>>(part, vvb, e, e2cat);

    // slot MLP: e2cat -> h1 -> e2 -> {k2h, edg}
    gemm_small<true, true, false, false><<<dim3(8, 16), 128, GS_SMEM_BYTES>>>(
        e2cat, Wm1T, nullptr, h1, nullptr, nullptr, bm1, nullptr, NS, HID, 2 * D);
    gemm_small<true, false, false, false><<<dim3(8, 16), 128, GS_SMEM_BYTES>>>(
        h1, Wm2T, nullptr, e2, nullptr, nullptr, bm2, nullptr, NS, D, HID);
    gemm_small<true, true, true, true><<<dim3(8, 16), 128, GS_SMEM_BYTES3>>>(
        e2, WkTf, cwT, nullptr, k2h, edg, bk, cb, NS, D, D);

    // FUSED dots2 + node attention
    dots2_node_fused<<<512, 256, FUS_SMEM_BYTES>>>(q2h, k2h, edg, nodesb, ndh);

    // FUSED tail + out (tmph never hits global memory)
    tail_out_fused<<<512, 256, TO_SMEM_BYTES>>>(
        xrh, ndh, Wc0h, Wc1h, Wth, bc01, bt, nodesb, out);
}

// round 15
// speedup vs baseline: 1.0100x; 1.0100x over previous
#include <cuda_runtime.h>
#include <cuda_fp16.h>
#include <math.h>
#include <stdint.h>

#define N_NODES 65536
#define D       256
#define NS      512
#define HID     256
#define KTOP    10
#define EPSC    1e-8f
#define SCALE_C 0.0625f  /* 256^-0.5 */

// ---------------------------------------------------------------------------
// Scratch
// ---------------------------------------------------------------------------
__device__ __half g_xh  [(size_t)N_NODES * D];
__device__ __half g_xrh [(size_t)N_NODES * D];
__device__ __half g_kkh [(size_t)N_NODES * D];
__device__ __half g_q2h [(size_t)N_NODES * D];
__device__ __half g_ndh [(size_t)N_NODES * D];
__device__ __half g_tmph[(size_t)N_NODES * D];
__device__ float  g_vv  [(size_t)N_NODES * D];
__device__ float  g_nodes[(size_t)N_NODES * D];
__device__ float  g_part[(size_t)NS * 512 * 24];

__device__ float  g_e    [NS * D];
__device__ __half g_qh   [NS * D];
__device__ __half g_k2h  [NS * D];
__device__ float  g_e2cat[NS * 2 * D];
__device__ float  g_h1   [NS * HID];
__device__ float  g_e2   [NS * D];
__device__ float  g_edg  [NS * D];

__device__ __half g_Wkvqh[3 * D * D];
__device__ __half g_Wc0h [D * D];
__device__ __half g_Wc1h [D * D];
__device__ __half g_Wth  [D * D];
__device__ float  g_bkvq [3 * D];
__device__ float  g_bc01 [D];
__device__ float  g_WqTf [D * D];
__device__ float  g_WkTf [D * D];
__device__ float  g_Wm1T [HID * 2 * D];
__device__ float  g_Wm2T [D * HID];
__device__ float  g_cwT  [D * D];

// ---------------------------------------------------------------------------
// helpers
// ---------------------------------------------------------------------------
__device__ __forceinline__ void mma16n8k16(float& c0, float& c1, float& c2, float& c3,
                                           uint32_t a0, uint32_t a1, uint32_t a2, uint32_t a3,
                                           uint32_t b0, uint32_t b1) {
    asm volatile(
        "mma.sync.aligned.m16n8k16.row.col.f32.f16.f16.f32 "
        "{%0,%1,%2,%3}, {%4,%5,%6,%7}, {%8,%9}, {%0,%1,%2,%3};"
        : "+f"(c0), "+f"(c1), "+f"(c2), "+f"(c3)
        : "r"(a0), "r"(a1), "r"(a2), "r"(a3), "r"(b0), "r"(b1));
}
__device__ __forceinline__ void ldsm_x4(uint32_t& r0, uint32_t& r1, uint32_t& r2, uint32_t& r3,
                                        uint32_t addr) {
    asm volatile("ldmatrix.sync.aligned.m8n8.x4.shared.b16 {%0,%1,%2,%3}, [%4];"
                 : "=r"(r0), "=r"(r1), "=r"(r2), "=r"(r3) : "r"(addr));
}
__device__ __forceinline__ void cp_async16(void* smem_dst, const void* gmem_src) {
    uint32_t d = (uint32_t)__cvta_generic_to_shared(smem_dst);
    asm volatile("cp.async.cg.shared.global [%0], [%1], 16;" :: "r"(d), "l"(gmem_src));
}
__device__ __forceinline__ void cp_commit() { asm volatile("cp.async.commit_group;"); }
__device__ __forceinline__ void cp_wait2()  { asm volatile("cp.async.wait_group 2;"); }
__device__ __forceinline__ void cp_wait0()  { asm volatile("cp.async.wait_group 0;"); }

#define LDH   40
#define HBUF  (128 * LDH)
#define MMA_SMEM_BYTES (6 * HBUF * 2)   /* 3-stage: 3 A + 3 B buffers */

struct FragOff {
    uint32_t a_off[2];
    uint32_t b_off[4];
};
__device__ __forceinline__ FragOff make_frag_off(int wid, int lane) {
    FragOff f;
    int warp_m = wid & 3, warp_n = wid >> 2;
#pragma unroll
    for (int mt = 0; mt < 2; mt++)
        f.a_off[mt] = ((warp_m * 32 + mt * 16 + (lane & 15)) * LDH + (lane >> 4) * 8) * 2;
    int b_row = (lane & 7) + ((lane >> 4) & 1) * 8;
    int b_koff = ((lane >> 3) & 1) * 8;
#pragma unroll
    for (int p = 0; p < 4; p++)
        f.b_off[p] = ((warp_n * 64 + p * 16 + b_row) * LDH + b_koff) * 2;
    return f;
}
#define MMA_COMPUTE_CHUNK(Ab, Bb, fo, acc)                                        \
    _Pragma("unroll")                                                             \
    for (int ks = 0; ks < 32; ks += 16) {                                         \
        uint32_t ra[2][4];                                                        \
        uint32_t rb[4][4];                                                        \
        _Pragma("unroll")                                                         \
        for (int mt = 0; mt < 2; mt++)                                            \
            ldsm_x4(ra[mt][0], ra[mt][1], ra[mt][2], ra[mt][3],                   \
                    (Ab) + (fo).a_off[mt] + ks * 2);                              \
        _Pragma("unroll")                                                         \
        for (int p = 0; p < 4; p++)                                               \
            ldsm_x4(rb[p][0], rb[p][1], rb[p][2], rb[p][3],                       \
                    (Bb) + (fo).b_off[p] + ks * 2);                               \
        _Pragma("unroll")                                                         \
        for (int p = 0; p < 4; p++)                                               \
            _Pragma("unroll")                                                     \
            for (int mt = 0; mt < 2; mt++) {                                      \
                mma16n8k16(acc[mt][2 * p][0], acc[mt][2 * p][1],                  \
                           acc[mt][2 * p][2], acc[mt][2 * p][3],                  \
                           ra[mt][0], ra[mt][1], ra[mt][2], ra[mt][3],            \
                           rb[p][0], rb[p][1]);                                   \
                mma16n8k16(acc[mt][2 * p + 1][0], acc[mt][2 * p + 1][1],          \
                           acc[mt][2 * p + 1][2], acc[mt][2 * p + 1][3],          \
                           ra[mt][0], ra[mt][1], ra[mt][2], ra[mt][3],            \
                           rb[p][2], rb[p][3]);                                   \
            }                                                                     \
    }

// 3-stage pipelined chunk loop (variadic: body may contain commas).
#define PIPE3_LOOP(NCHv, LOADFN, ...)                                             \
    LOADFN(0, 0); cp_commit();                                                    \
    LOADFN(1, 1); cp_commit();                                                    \
    for (int ch = 0; ch < (NCHv); ch++) {                                         \
        if (ch + 2 < (NCHv)) LOADFN(ch + 2, (ch + 2) % 3);                        \
        cp_commit();                                                              \
        cp_wait2();                                                               \
        __syncthreads();                                                          \
        { __VA_ARGS__ }                                                           \
        __syncthreads();                                                          \
    }

// ---------------------------------------------------------------------------
// Pipelined fp16 NT GEMM. EPI: 2 = C=relu(acc+bias) fp32, 4 = kvq split
// ---------------------------------------------------------------------------
template <int EPI>
__global__ void __launch_bounds__(256) mma_gemm(
    const __half* __restrict__ A, const __half* __restrict__ B,
    float* __restrict__ C, const float* __restrict__ bias,
    float* __restrict__ Cf2, __half* __restrict__ Ch, __half* __restrict__ Ch2,
    int M, int Ntot, int K) {
    extern __shared__ __half smh[];
    const int tid = threadIdx.x;
    const int wid = tid >> 5, lane = tid & 31;
    const int warp_m = wid & 3;
    const int warp_n = wid >> 2;
    const int bm = blockIdx.y * 128;
    const int bn = blockIdx.x * 128;
    const int grp = lane >> 2;
    const int tig = lane & 3;
    const uint32_t smb = (uint32_t)__cvta_generic_to_shared(smh);
    FragOff fo = make_frag_off(wid, lane);

    float acc[2][8][4];
#pragma unroll
    for (int i = 0; i < 2; i++)
#pragma unroll
        for (int j = 0; j < 8; j++)
#pragma unroll
            for (int r = 0; r < 4; r++) acc[i][j][r] = 0.f;

    const int NCH = K >> 5;
    auto load_tile = [&](int ch, int buf) {
        const __half* Ag = A + (size_t)bm * K + ch * 32;
        const __half* Bg = B + (size_t)bn * K + ch * 32;
        __half* Ad = smh + buf * HBUF;
        __half* Bd = smh + (3 + buf) * HBUF;
#pragma unroll
        for (int i = 0; i < 2; i++) {
            int id = tid + (i << 8);
            int row = id >> 2, c8 = (id & 3) << 3;
            cp_async16(Ad + row * LDH + c8, Ag + (size_t)row * K + c8);
            cp_async16(Bd + row * LDH + c8, Bg + (size_t)row * K + c8);
        }
    };

    PIPE3_LOOP(NCH, load_tile,
        const uint32_t Ab = smb + (ch % 3) * HBUF * 2;
        const uint32_t Bb = smb + (3 + ch % 3) * HBUF * 2;
        MMA_COMPUTE_CHUNK(Ab, Bb, fo, acc);
    )

#pragma unroll
    for (int mt = 0; mt < 2; mt++) {
        int r0 = bm + warp_m * 32 + mt * 16 + grp;
#pragma unroll
        for (int nt = 0; nt < 8; nt++) {
            int c0 = bn + warp_n * 64 + nt * 8 + 2 * tig;
#pragma unroll
            for (int half_ = 0; half_ < 2; half_++) {
                int rr = r0 + half_ * 8;
                float vx = acc[mt][nt][2 * half_ + 0] + bias[c0];
                float vy = acc[mt][nt][2 * half_ + 1] + bias[c0 + 1];
                if constexpr (EPI == 4) {
                    int seg = c0 >> 8;
                    size_t idx = (size_t)rr * D + (c0 & 255);
                    if (seg == 0) {
                        vx = fmaxf(vx, 0.f); vy = fmaxf(vy, 0.f);
                        *reinterpret_cast<__half2*>(Ch + idx) = __floats2half2_rn(vx, vy);
                    } else if (seg == 1) {
                        vx = fmaxf(vx, 0.f); vy = fmaxf(vy, 0.f);
                        float2 o; o.x = vx; o.y = vy;
                        *reinterpret_cast<float2*>(Cf2 + idx) = o;
                    } else {
                        *reinterpret_cast<__half2*>(Ch2 + idx) = __floats2half2_rn(vx, vy);
                    }
                } else {
                    vx = fmaxf(vx, 0.f); vy = fmaxf(vy, 0.f);
                    size_t idx = (size_t)rr * Ntot + c0;
                    float2 o; o.x = vx; o.y = vy;
                    *reinterpret_cast<float2*>(C + idx) = o;
                }
            }
        }
    }
}

// ---------------------------------------------------------------------------
// Tail fused GEMM: Ch = relu( [A1|A2] @ [B1;B2]^T + bias + aux )  (K=512)
// ---------------------------------------------------------------------------
__global__ void __launch_bounds__(256) mma_gemm_tail(
    const __half* __restrict__ A1, const __half* __restrict__ A2,
    const __half* __restrict__ B1, const __half* __restrict__ B2,
    const float* __restrict__ bias, const float* __restrict__ aux,
    __half* __restrict__ Ch) {
    extern __shared__ __half smh[];
    const int tid = threadIdx.x;
    const int wid = tid >> 5, lane = tid & 31;
    const int warp_m = wid & 3;
    const int warp_n = wid >> 2;
    const int bm = blockIdx.y * 128;
    const int bn = blockIdx.x * 128;
    const int grp = lane >> 2;
    const int tig = lane & 3;
    const int K = D;
    const uint32_t smb = (uint32_t)__cvta_generic_to_shared(smh);
    FragOff fo = make_frag_off(wid, lane);

    float acc[2][8][4];
#pragma unroll
    for (int i = 0; i < 2; i++)
#pragma unroll
        for (int j = 0; j < 8; j++)
#pragma unroll
            for (int r = 0; r < 4; r++) acc[i][j][r] = 0.f;

    auto load_tile = [&](int ch, int buf) {
        const __half* Ag = (ch < 8) ? A1 + (size_t)bm * K + ch * 32
                                    : A2 + (size_t)bm * K + (ch - 8) * 32;
        const __half* Bg = (ch < 8) ? B1 + (size_t)bn * K + ch * 32
                                    : B2 + (size_t)bn * K + (ch - 8) * 32;
        __half* Ad = smh + buf * HBUF;
        __half* Bd = smh + (3 + buf) * HBUF;
#pragma unroll
        for (int i = 0; i < 2; i++) {
            int id = tid + (i << 8);
            int row = id >> 2, c8 = (id & 3) << 3;
            cp_async16(Ad + row * LDH + c8, Ag + (size_t)row * K + c8);
            cp_async16(Bd + row * LDH + c8, Bg + (size_t)row * K + c8);
        }
    };

    PIPE3_LOOP(16, load_tile,
        const uint32_t Ab = smb + (ch % 3) * HBUF * 2;
        const uint32_t Bb = smb + (3 + ch % 3) * HBUF * 2;
        MMA_COMPUTE_CHUNK(Ab, Bb, fo, acc);
    )

#pragma unroll
    for (int mt = 0; mt < 2; mt++) {
        int r0 = bm + warp_m * 32 + mt * 16 + grp;
#pragma unroll
        for (int nt = 0; nt < 8; nt++) {
            int c0 = bn + warp_n * 64 + nt * 8 + 2 * tig;
#pragma unroll
            for (int half_ = 0; half_ < 2; half_++) {
                int rr = r0 + half_ * 8;
                size_t idx = (size_t)rr * D + c0;
                float2 aa = *reinterpret_cast<const float2*>(aux + idx);
                float vx = fmaxf(acc[mt][nt][2 * half_ + 0] + bias[c0] + aa.x, 0.f);
                float vy = fmaxf(acc[mt][nt][2 * half_ + 1] + bias[c0 + 1] + aa.y, 0.f);
                *reinterpret_cast<__half2*>(Ch + idx) = __floats2half2_rn(vx, vy);
            }
        }
    }
}

// ---------------------------------------------------------------------------
// FUSED dots2 + node attention
// ---------------------------------------------------------------------------
#define LGD 133
#define FUS_SMEM_BYTES (128 * LGD * 4 + 128 * KTOP * 4 + 128 * KTOP * 4)

__global__ void __launch_bounds__(256) dots2_node_fused(
    const __half* __restrict__ A, const __half* __restrict__ Bk,
    const float* __restrict__ edg,
    float* __restrict__ nodes, __half* __restrict__ nodesh) {
    extern __shared__ __half smh[];
    float* logits = reinterpret_cast<float*>(smh);
    float* wv_s = logits + 128 * LGD;
    int*   wi_s = reinterpret_cast<int*>(wv_s + 128 * KTOP);

    const int tid = threadIdx.x;
    const int wid = tid >> 5, lane = tid & 31;
    const int warp_m = wid & 3;
    const int warp_n = wid >> 2;
    const int bm = blockIdx.x * 128;
    const int grp = lane >> 2;
    const int tig = lane & 3;
    const int K = D;
    const uint32_t smb = (uint32_t)__cvta_generic_to_shared(smh);
    FragOff fo = make_frag_off(wid, lane);

    float m_run = -INFINITY, z_run = 0.f;
    float tv[KTOP]; int ti[KTOP];
#pragma unroll
    for (int i = 0; i < KTOP; i++) { tv[i] = -INFINITY; ti[i] = 0; }

    for (int sc = 0; sc < 4; sc++) {
        float acc[2][8][4];
#pragma unroll
        for (int i = 0; i < 2; i++)
#pragma unroll
            for (int j = 0; j < 8; j++)
#pragma unroll
                for (int r = 0; r < 4; r++) acc[i][j][r] = 0.f;

        const __half* Bg_base = Bk + (size_t)(sc * 128) * K;
        auto load_tile = [&](int ch, int buf) {
            const __half* Ag = A + (size_t)bm * K + ch * 32;
            const __half* Bg = Bg_base + ch * 32;
            __half* Ad = smh + buf * HBUF;
            __half* Bd = smh + (3 + buf) * HBUF;
#pragma unroll
            for (int i = 0; i < 2; i++) {
                int id = tid + (i << 8);
                int row = id >> 2, c8 = (id & 3) << 3;
                cp_async16(Ad + row * LDH + c8, Ag + (size_t)row * K + c8);
                cp_async16(Bd + row * LDH + c8, Bg + (size_t)row * K + c8);
            }
        };

        PIPE3_LOOP(8, load_tile,
            const uint32_t Ab = smb + (ch % 3) * HBUF * 2;
            const uint32_t Bb = smb + (3 + ch % 3) * HBUF * 2;
            MMA_COMPUTE_CHUNK(Ab, Bb, fo, acc);
        )

#pragma unroll
        for (int mt = 0; mt < 2; mt++) {
            int r0 = warp_m * 32 + mt * 16 + grp;
#pragma unroll
            for (int nt = 0; nt < 8; nt++) {
                int c0 = warp_n * 64 + nt * 8 + 2 * tig;
#pragma unroll
                for (int half_ = 0; half_ < 2; half_++) {
                    int rr = r0 + half_ * 8;
                    logits[rr * LGD + c0]     = acc[mt][nt][2 * half_ + 0] * SCALE_C;
                    logits[rr * LGD + c0 + 1] = acc[mt][nt][2 * half_ + 1] * SCALE_C;
                }
            }
        }
        __syncthreads();
        if (tid < 128) {
            const float* lr = logits + tid * LGD;
            for (int j = 0; j < 128; j++) {
                float v = lr[j];
                if (v > m_run) { z_run *= __expf(m_run - v); m_run = v; }
                z_run += __expf(v - m_run);
                if (v > tv[KTOP - 1]) {
                    int ix = sc * 128 + j;
                    float vt = v;
#pragma unroll
                    for (int p = 0; p < KTOP; p++)
                        if (vt > tv[p]) {
                            float tf = tv[p]; tv[p] = vt; vt = tf;
                            int tt = ti[p]; ti[p] = ix; ix = tt;
                        }
                }
            }
        }
        __syncthreads();
    }
    if (tid < 128) {
        float zin = 1.f / z_run;
#pragma unroll
        for (int i = 0; i < KTOP; i++) {
            wv_s[tid * KTOP + i] = __expf(tv[i] - m_run) * zin;
            wi_s[tid * KTOP + i] = ti[i];
        }
    }
    __syncthreads();
    for (int rr = 0; rr < 16; rr++) {
        int r = wid * 16 + rr;
        float w_[KTOP]; int ix_[KTOP];
#pragma unroll
        for (int i = 0; i < KTOP; i++) { w_[i] = wv_s[r * KTOP + i]; ix_[i] = wi_s[r * KTOP + i]; }
        float* po = nodes + (size_t)(bm + r) * D;
        __half* ph = nodesh + (size_t)(bm + r) * D;
#pragma unroll
        for (int j = 0; j < 8; j++) {
            int c = lane + 32 * j;
            float a2 = 0.f;
#pragma unroll
            for (int i = 0; i < KTOP; i++) a2 += w_[i] * edg[(size_t)ix_[i] * D + c];
            po[c] = a2;
            ph[c] = __float2half_rn(a2);
        }
    }
}

// ---------------------------------------------------------------------------
// dots1 Phase A
// ---------------------------------------------------------------------------
#define FUS1_SMEM_BYTES (128 * LGD * 4)

__global__ void __launch_bounds__(256) dots1_partial(
    const __half* __restrict__ A, const __half* __restrict__ Bk,
    float* __restrict__ part) {
    extern __shared__ __half smh[];
    float* logits = reinterpret_cast<float*>(smh);
    const int tid = threadIdx.x;
    const int wid = tid >> 5, lane = tid & 31;
    const int warp_m = wid & 3;
    const int warp_n = wid >> 2;
    const int bm = blockIdx.y * 128;
    const int bnc = blockIdx.x;
    const int grp = lane >> 2;
    const int tig = lane & 3;
    const int K = D;
    const uint32_t smb = (uint32_t)__cvta_generic_to_shared(smh);
    FragOff fo = make_frag_off(wid, lane);

    float acc[2][8][4];
#pragma unroll
    for (int i = 0; i < 2; i++)
#pragma unroll
        for (int j = 0; j < 8; j++)
#pragma unroll
            for (int r = 0; r < 4; r++) acc[i][j][r] = 0.f;

    const __half* Bg_base = Bk + (size_t)bnc * 128 * K;
    auto load_tile = [&](int ch, int buf) {
        const __half* Ag = A + (size_t)bm * K + ch * 32;
        const __half* Bg = Bg_base + ch * 32;
        __half* Ad = smh + buf * HBUF;
        __half* Bd = smh + (3 + buf) * HBUF;
#pragma unroll
        for (int i = 0; i < 2; i++) {
            int id = tid + (i << 8);
            int row = id >> 2, c8 = (id & 3) << 3;
            cp_async16(Ad + row * LDH + c8, Ag + (size_t)row * K + c8);
            cp_async16(Bd + row * LDH + c8, Bg + (size_t)row * K + c8);
        }
    };

    PIPE3_LOOP(8, load_tile,
        const uint32_t Ab = smb + (ch % 3) * HBUF * 2;
        const uint32_t Bb = smb + (3 + ch % 3) * HBUF * 2;
        MMA_COMPUTE_CHUNK(Ab, Bb, fo, acc);
    )

#pragma unroll
    for (int mt = 0; mt < 2; mt++) {
        int r0 = warp_m * 32 + mt * 16 + grp;
#pragma unroll
        for (int nt = 0; nt < 8; nt++) {
            int c0 = warp_n * 64 + nt * 8 + 2 * tig;
#pragma unroll
            for (int half_ = 0; half_ < 2; half_++) {
                int rr = r0 + half_ * 8;
                logits[rr * LGD + c0]     = acc[mt][nt][2 * half_ + 0] * SCALE_C;
                logits[rr * LGD + c0 + 1] = acc[mt][nt][2 * half_ + 1] * SCALE_C;
            }
        }
    }
    __syncthreads();
    if (tid < 128) {
        const float* lr = logits + tid * LGD;
        float m = -INFINITY, z = 0.f;
        float tv[KTOP]; int ti[KTOP];
#pragma unroll
        for (int i = 0; i < KTOP; i++) { tv[i] = -INFINITY; ti[i] = 0; }
        for (int j = 0; j < 128; j++) {
            float v = lr[j];
            if (v > m) { z *= __expf(m - v); m = v; }
            z += __expf(v - m);
            if (v > tv[KTOP - 1]) {
                int ix = bnc * 128 + j;
                float vt = v;
#pragma unroll
                for (int p = 0; p < KTOP; p++)
                    if (vt > tv[p]) {
                        float tf = tv[p]; tv[p] = vt; vt = tf;
                        int tt = ti[p]; ti[p] = ix; ix = tt;
                    }
            }
        }
        float* rec = part + ((size_t)(bm + tid) * 512 + bnc) * 24;
        rec[0] = m; rec[1] = z;
#pragma unroll
        for (int i = 0; i < KTOP; i++) {
            rec[2 + i] = tv[i];
            rec[12 + i] = __int_as_float(ti[i]);
        }
    }
}

// ---------------------------------------------------------------------------
// dots1 Phase B merge
// ---------------------------------------------------------------------------
__global__ void slot_merge(const float* __restrict__ part, const float* __restrict__ vv,
                           const float* __restrict__ e, float* __restrict__ e2cat) {
    __shared__ float sv[256 * KTOP];
    __shared__ int   si[256 * KTOP];
    __shared__ float sm_m[256];
    __shared__ float sm_z[256];
    __shared__ float sw[KTOP];
    __shared__ int   sx[KTOP];
    int s = blockIdx.x, tid = threadIdx.x;

    const float* r0 = part + ((size_t)s * 512 + 2 * tid) * 24;
    const float* r1 = r0 + 24;
    float m = r0[0], z = r0[1];
    float tv[KTOP]; int ti[KTOP];
#pragma unroll
    for (int i = 0; i < KTOP; i++) { tv[i] = r0[2 + i]; ti[i] = __float_as_int(r0[12 + i]); }
    {
        float mb = r1[0], zb = r1[1];
        float mn = fmaxf(m, mb);
        z = z * __expf(m - mn) + zb * __expf(mb - mn);
        m = mn;
#pragma unroll
        for (int i = 0; i < KTOP; i++) {
            float v = r1[2 + i];
            int ix = __float_as_int(r1[12 + i]);
            if (v > tv[KTOP - 1]) {
#pragma unroll
                for (int p = 0; p < KTOP; p++)
                    if (v > tv[p]) {
                        float tf = tv[p]; tv[p] = v; v = tf;
                        int tt = ti[p]; ti[p] = ix; ix = tt;
                    }
            }
        }
    }
#pragma unroll
    for (int i = 0; i < KTOP; i++) { sv[tid * KTOP + i] = tv[i]; si[tid * KTOP + i] = ti[i]; }
    sm_m[tid] = m; sm_z[tid] = z;
    __syncthreads();
    for (int stride = 128; stride >= 1; stride >>= 1) {
        if (tid < stride) {
#pragma unroll
            for (int i = 0; i < KTOP; i++) { tv[i] = sv[tid * KTOP + i]; ti[i] = si[tid * KTOP + i]; }
#pragma unroll
            for (int i = 0; i < KTOP; i++) {
                float v = sv[(tid + stride) * KTOP + i];
                int ix = si[(tid + stride) * KTOP + i];
                if (v > tv[KTOP - 1]) {
#pragma unroll
                    for (int p = 0; p < KTOP; p++)
                        if (v > tv[p]) {
                            float tf = tv[p]; tv[p] = v; v = tf;
                            int tt = ti[p]; ti[p] = ix; ix = tt;
                        }
                }
            }
#pragma unroll
            for (int i = 0; i < KTOP; i++) { sv[tid * KTOP + i] = tv[i]; si[tid * KTOP + i] = ti[i]; }
            float ma = sm_m[tid], za = sm_z[tid];
            float mb = sm_m[tid + stride], zb = sm_z[tid + stride];
            float mn = fmaxf(ma, mb);
            float zn = za * __expf(ma - mn) + zb * __expf(mb - mn);
            sm_m[tid] = mn; sm_z[tid] = zn;
        }
        __syncthreads();
    }
    float maxv = sm_m[0];
    float Z = sm_z[0];
    if (tid < KTOP) {
        float p = __expf(sv[tid] - maxv) / Z;
        sw[tid] = (p + EPSC) / (1.f + (float)N_NODES * EPSC);
        sx[tid] = si[tid];
    }
    __syncthreads();
    float acc = 0.f;
#pragma unroll
    for (int i = 0; i < KTOP; i++) acc += sw[i] * vv[(size_t)sx[i] * D + tid];
    e2cat[(size_t)s * 2 * D + D + tid] = acc;
    e2cat[(size_t)s * 2 * D + tid] = e[(size_t)s * D + tid];
}

// ---------------------------------------------------------------------------
// prep: weight transposes + bias tasks + edges LN. grid (64, 14), block (32,8)
// ---------------------------------------------------------------------------
__device__ __forceinline__ void tr_tile(const float* in, float* outF, __half* outH,
                                        int R, int C, int bx, float (*tile)[33]) {
    int tx = threadIdx.x, tyw = threadIdx.y;
    int xt = bx & (C / 32 - 1), yt = bx / (C / 32);
    int bxc = xt * 32, byr = yt * 32;
    for (int y = tyw; y < 32; y += 8)
        tile[y][tx] = in[(size_t)(byr + y) * C + bxc + tx];
    __syncthreads();
    if (outH) {
        for (int y = tyw; y < 32; y += 8)
            outH[(size_t)(bxc + y) * R + byr + tx] = __float2half_rn(tile[tx][y]);
    } else {
        for (int y = tyw; y < 32; y += 8)
            outF[(size_t)(bxc + y) * R + byr + tx] = tile[tx][y];
    }
}

__global__ void prep(
    const float* Wk, const float* Wv, const float* Wq, const float* Wc0,
    const float* Wc1, const float* Wt, const float* cw, const float* Wm1,
    const float* Wm2,
    __half* Wkvqh, __half* Wc0h, __half* Wc1h, __half* Wth,
    float* WqTf, float* WkTf, float* cwT, float* Wm1T, float* Wm2T,
    const float* bk, const float* bv, const float* bq, float* bkvq,
    const float* bc0, const float* bc1, float* bc01,
    const float* noise, const float* emu, const float* elog,
    const float* lew, const float* leb, float* e) {
    __shared__ float tile[32][33];
    int task = blockIdx.y, bx = blockIdx.x;
    switch (task) {
    case 0: tr_tile(Wk,  nullptr, Wkvqh,             D, D, bx, tile); break;
    case 1: tr_tile(Wv,  nullptr, Wkvqh + D * D,     D, D, bx, tile); break;
    case 2: tr_tile(Wq,  nullptr, Wkvqh + 2 * D * D, D, D, bx, tile); break;
    case 3: tr_tile(Wc0, nullptr, Wc0h, D, D, bx, tile); break;
    case 4: tr_tile(Wc1, nullptr, Wc1h, D, D, bx, tile); break;
    case 5: tr_tile(Wt,  nullptr, Wth,  D, D, bx, tile); break;
    case 6: tr_tile(Wq,  WqTf, nullptr, D, D, bx, tile); break;
    case 7: tr_tile(Wk,  WkTf, nullptr, D, D, bx, tile); break;
    case 8: tr_tile(cw,  cwT,  nullptr, D, D, bx, tile); break;
    case 9: tr_tile(Wm2, Wm2T, nullptr, HID, D, bx, tile); break;
    case 10: tr_tile(Wm1, Wm1T, nullptr, 2 * D, HID, bx, tile); break;
    case 11: tr_tile(Wm1, Wm1T, nullptr, 2 * D, HID, bx + 64, tile); break;
    case 12: {
        if (bx == 0) {
            int i = threadIdx.y * 32 + threadIdx.x;
            bkvq[i] = bk[i]; bkvq[D + i] = bv[i]; bkvq[2 * D + i] = bq[i];
            bc01[i] = bc0[i] + bc1[i];
        }
        break;
    }
    default: {  // 13: edges LN
        int warp = bx * 8 + threadIdx.y;
        int lane = threadIdx.x;
        const float* r = noise + (size_t)warp * D;
        float v[8]; float s = 0.f;
#pragma unroll
        for (int j = 0; j < 8; j++) {
            int c = lane + 32 * j;
            v[j] = emu[c] + expf(elog[c]) * r[c];
            s += v[j];
        }
#pragma unroll
        for (int st = 16; st; st >>= 1) s += __shfl_xor_sync(0xffffffffu, s, st);
        float mu = s * (1.f / 256.f);
        float q = 0.f;
#pragma unroll
        for (int j = 0; j < 8; j++) { float d2 = v[j] - mu; q += d2 * d2; }
#pragma unroll
        for (int st = 16; st; st >>= 1) q += __shfl_xor_sync(0xffffffffu, q, st);
        float rinv = rsqrtf(q * (1.f / 256.f) + 1e-5f);
        float* po = e + (size_t)warp * D;
#pragma unroll
        for (int j = 0; j < 8; j++) {
            int c = lane + 32 * j;
            po[c] = (v[j] - mu) * rinv * lew[c] + leb[c];
        }
        break;
    }
    }
}

// ---------------------------------------------------------------------------
// LayerNorm -> half + x->half copy
// ---------------------------------------------------------------------------
__global__ void ln_rows(const float* __restrict__ x, const float* __restrict__ w,
                        const float* __restrict__ b, __half* __restrict__ o,
                        __half* __restrict__ xrh, int M) {
    int warp = (blockIdx.x * blockDim.x + threadIdx.x) >> 5;
    int lane = threadIdx.x & 31;
    if (warp >= M) return;
    const float* r = x + (size_t)warp * D;
    float v[8]; float s = 0.f;
#pragma unroll
    for (int j = 0; j < 8; j++) { v[j] = r[lane + 32 * j]; s += v[j]; }
#pragma unroll
    for (int st = 16; st; st >>= 1) s += __shfl_xor_sync(0xffffffffu, s, st);
    float mu = s * (1.f / 256.f);
    float q = 0.f;
#pragma unroll
    for (int j = 0; j < 8; j++) { float d = v[j] - mu; q += d * d; }
#pragma unroll
    for (int st = 16; st; st >>= 1) q += __shfl_xor_sync(0xffffffffu, q, st);
    float rinv = rsqrtf(q * (1.f / 256.f) + 1e-5f);
    __half* po = o + (size_t)warp * D;
    __half* px = xrh + (size_t)warp * D;
#pragma unroll
    for (int j = 0; j < 8; j++) {
        int c = lane + 32 * j;
        po[c] = __float2half_rn((v[j] - mu) * rinv * w[c] + b[c]);
        px[c] = __float2half_rn(v[j]);
    }
}

// ---------------------------------------------------------------------------
// Small fp32 NT GEMM: 32x32 tile, 128 threads. DUAL variant: second B.
// ---------------------------------------------------------------------------
#define GSW 260
#define GS_SMEM_BYTES  (2 * 32 * GSW * 4)
#define GS_SMEM_BYTES3 (3 * 32 * GSW * 4)

template <bool BIAS, bool RELU, bool OUTH, bool DUAL>
__global__ void __launch_bounds__(128) gemm_small(
    const float* __restrict__ A, const float* __restrict__ B,
    const float* __restrict__ B2d,
    float* __restrict__ C, __half* __restrict__ Ch, float* __restrict__ C2,
    const float* __restrict__ bias, const float* __restrict__ bias2,
    int M, int N, int K) {
    extern __shared__ float gs[];
    float* As = gs;
    float* Bs = gs + 32 * GSW;
    float* B2s = gs + 2 * 32 * GSW;
    const int tid = threadIdx.x;
    const int tx = tid & 7, ty = tid >> 3;
    const int bm = blockIdx.y * 32, bn = blockIdx.x * 32;

    float acc[2][4], acc2[2][4];
#pragma unroll
    for (int i = 0; i < 2; i++)
#pragma unroll
        for (int j = 0; j < 4; j++) { acc[i][j] = 0.f; acc2[i][j] = 0.f; }

    for (int k0 = 0; k0 < K; k0 += 256) {
#pragma unroll
        for (int i = 0; i < 16; i++) {
            int id = tid + i * 128;
            int row = id >> 6, c4 = (id & 63) << 2;
            cp_async16(&As[row * GSW + c4], &A[(size_t)(bm + row) * K + k0 + c4]);
            cp_async16(&Bs[row * GSW + c4], &B[(size_t)(bn + row) * K + k0 + c4]);
            if (DUAL)
                cp_async16(&B2s[row * GSW + c4], &B2d[(size_t)(bn + row) * K + k0 + c4]);
        }
        cp_commit();
        cp_wait0();
        __syncthreads();
#pragma unroll 4
        for (int k = 0; k < 256; k += 4) {
            float4 a0 = *reinterpret_cast<const float4*>(&As[(ty * 2 + 0) * GSW + k]);
            float4 a1 = *reinterpret_cast<const float4*>(&As[(ty * 2 + 1) * GSW + k]);
#pragma unroll
            for (int j = 0; j < 4; j++) {
                float4 b4 = *reinterpret_cast<const float4*>(&Bs[(tx + 8 * j) * GSW + k]);
                acc[0][j] += a0.x * b4.x + a0.y * b4.y + a0.z * b4.z + a0.w * b4.w;
                acc[1][j] += a1.x * b4.x + a1.y * b4.y + a1.z * b4.z + a1.w * b4.w;
                if (DUAL) {
                    float4 c4v = *reinterpret_cast<const float4*>(&B2s[(tx + 8 * j) * GSW + k]);
                    acc2[0][j] += a0.x * c4v.x + a0.y * c4v.y + a0.z * c4v.z + a0.w * c4v.w;
                    acc2[1][j] += a1.x * c4v.x + a1.y * c4v.y + a1.z * c4v.z + a1.w * c4v.w;
                }
            }
        }
        __syncthreads();
    }
#pragma unroll
    for (int i = 0; i < 2; i++) {
        int m = bm + ty * 2 + i;
#pragma unroll
        for (int j = 0; j < 4; j++) {
            int n = bn + tx + 8 * j;
            float v = acc[i][j];
            if (BIAS) v += bias[n];
            if (RELU) v = fmaxf(v, 0.f);
            if (OUTH) Ch[(size_t)m * N + n] = __float2half_rn(v);
            else      C [(size_t)m * N + n] = v;
            if (DUAL) {
                float v2 = acc2[i][j] + bias2[n];
                C2[(size_t)m * N + n] = v2;
            }
        }
    }
}

// ---------------------------------------------------------------------------
// Launch
// ---------------------------------------------------------------------------
extern "C" void kernel_launch(void* const* d_in, const int* in_sizes, int n_in,
                              void* d_out, int out_size) {
    (void)in_sizes; (void)n_in; (void)out_size;
    const float* x      = (const float*)d_in[0];
    const float* enoise = (const float*)d_in[1];
    const float* emu    = (const float*)d_in[2];
    const float* elog   = (const float*)d_in[3];
    const float* lnw    = (const float*)d_in[4];
    const float* lnb    = (const float*)d_in[5];
    const float* lew    = (const float*)d_in[6];
    const float* leb    = (const float*)d_in[7];
    const float* Wq = (const float*)d_in[8];  const float* bq = (const float*)d_in[9];
    const float* Wk = (const float*)d_in[10]; const float* bk = (const float*)d_in[11];
    const float* Wv = (const float*)d_in[12]; const float* bv = (const float*)d_in[13];
    const float* Wm1 = (const float*)d_in[14]; const float* bm1 = (const float*)d_in[15];
    const float* Wm2 = (const float*)d_in[16]; const float* bm2 = (const float*)d_in[17];
    const float* cw = (const float*)d_in[18];  const float* cb = (const float*)d_in[19];
    const float* Wc0 = (const float*)d_in[20]; const float* bc0 = (const float*)d_in[21];
    const float* Wc1 = (const float*)d_in[22]; const float* bc1 = (const float*)d_in[23];
    const float* Wt = (const float*)d_in[24];  const float* bt = (const float*)d_in[25];
    float* out = (float*)d_out;

    void* p;
    cudaGetSymbolAddress(&p, g_xh);    __half* xh = (__half*)p;
    cudaGetSymbolAddress(&p, g_xrh);   __half* xrh = (__half*)p;
    cudaGetSymbolAddress(&p, g_kkh);   __half* kkh = (__half*)p;
    cudaGetSymbolAddress(&p, g_q2h);   __half* q2h = (__half*)p;
    cudaGetSymbolAddress(&p, g_ndh);   __half* ndh = (__half*)p;
    cudaGetSymbolAddress(&p, g_tmph);  __half* tmph = (__half*)p;
    cudaGetSymbolAddress(&p, g_vv);    float* vvb = (float*)p;
    cudaGetSymbolAddress(&p, g_nodes); float* nodesb = (float*)p;
    cudaGetSymbolAddress(&p, g_part);  float* part = (float*)p;
    cudaGetSymbolAddress(&p, g_e);     float* e = (float*)p;
    cudaGetSymbolAddress(&p, g_qh);    __half* qh = (__half*)p;
    cudaGetSymbolAddress(&p, g_k2h);   __half* k2h = (__half*)p;
    cudaGetSymbolAddress(&p, g_e2cat); float* e2cat = (float*)p;
    cudaGetSymbolAddress(&p, g_h1);    float* h1 = (float*)p;
    cudaGetSymbolAddress(&p, g_e2);    float* e2 = (float*)p;
    cudaGetSymbolAddress(&p, g_edg);   float* edg = (float*)p;
    cudaGetSymbolAddress(&p, g_Wkvqh); __half* Wkvqh = (__half*)p;
    cudaGetSymbolAddress(&p, g_Wc0h);  __half* Wc0h = (__half*)p;
    cudaGetSymbolAddress(&p, g_Wc1h);  __half* Wc1h = (__half*)p;
    cudaGetSymbolAddress(&p, g_Wth);   __half* Wth = (__half*)p;
    cudaGetSymbolAddress(&p, g_bkvq);  float* bkvq = (float*)p;
    cudaGetSymbolAddress(&p, g_bc01);  float* bc01 = (float*)p;
    cudaGetSymbolAddress(&p, g_WqTf);  float* WqTf = (float*)p;
    cudaGetSymbolAddress(&p, g_WkTf);  float* WkTf = (float*)p;
    cudaGetSymbolAddress(&p, g_Wm1T);  float* Wm1T = (float*)p;
    cudaGetSymbolAddress(&p, g_Wm2T);  float* Wm2T = (float*)p;
    cudaGetSymbolAddress(&p, g_cwT);   float* cwT = (float*)p;

    cudaFuncSetAttribute(mma_gemm<2>, cudaFuncAttributeMaxDynamicSharedMemorySize, MMA_SMEM_BYTES);
    cudaFuncSetAttribute(mma_gemm<4>, cudaFuncAttributeMaxDynamicSharedMemorySize, MMA_SMEM_BYTES);
    cudaFuncSetAttribute(mma_gemm_tail, cudaFuncAttributeMaxDynamicSharedMemorySize, MMA_SMEM_BYTES);
    cudaFuncSetAttribute(dots2_node_fused, cudaFuncAttributeMaxDynamicSharedMemorySize, FUS_SMEM_BYTES);
    cudaFuncSetAttribute(dots1_partial, cudaFuncAttributeMaxDynamicSharedMemorySize, FUS1_SMEM_BYTES);
    cudaFuncSetAttribute(gemm_small<true, true, true, false>, cudaFuncAttributeMaxDynamicSharedMemorySize, GS_SMEM_BYTES);
    cudaFuncSetAttribute(gemm_small<true, true, false, false>, cudaFuncAttributeMaxDynamicSharedMemorySize, GS_SMEM_BYTES);
    cudaFuncSetAttribute(gemm_small<true, false, false, false>, cudaFuncAttributeMaxDynamicSharedMemorySize, GS_SMEM_BYTES);
    cudaFuncSetAttribute(gemm_small<true, true, true, true>, cudaFuncAttributeMaxDynamicSharedMemorySize, GS_SMEM_BYTES3);

    prep<<<dim3(64, 14), dim3(32, 8)>>>(
        Wk, Wv, Wq, Wc0, Wc1, Wt, cw, Wm1, Wm2,
        Wkvqh, Wc0h, Wc1h, Wth, WqTf, WkTf, cwT, Wm1T, Wm2T,
        bk, bv, bq, bkvq, bc0, bc1, bc01,
        enoise, emu, elog, lew, leb, e);

    ln_rows<<<N_NODES / 8, 256>>>(x, lnw, lnb, xh, xrh, N_NODES);

    // fused: kk(half,relu), vv(fp32,relu), q2(half)
    mma_gemm<4><<<dim3(6, 512), 256, MMA_SMEM_BYTES>>>(
        xh, Wkvqh, nullptr, bkvq, vvb, kkh, q2h, N_NODES, 3 * D, D);

    // q = relu(e@Wq+bq) -> half
    gemm_small<true, true, true, false><<<dim3(8, 16), 128, GS_SMEM_BYTES>>>(
        e, WqTf, nullptr, nullptr, qh, nullptr, bq, nullptr, NS, D, D);

    // dots1 partials + merge
    dots1_partial<<<dim3(512, 4), 256, FUS1_SMEM_BYTES>>>(qh, kkh, part);
    slot_merge<<<NS, 256>>>(part, vvb, e, e2cat);

    // slot MLP: e2cat -> h1 -> e2 -> {k2h, edg}
    gemm_small<true, true, false, false><<<dim3(8, 16), 128, GS_SMEM_BYTES>>>(
        e2cat, Wm1T, nullptr, h1, nullptr, nullptr, bm1, nullptr, NS, HID, 2 * D);
    gemm_small<true, false, false, false><<<dim3(8, 16), 128, GS_SMEM_BYTES>>>(
        h1, Wm2T, nullptr, e2, nullptr, nullptr, bm2, nullptr, NS, D, HID);
    gemm_small<true, true, true, true><<<dim3(8, 16), 128, GS_SMEM_BYTES3>>>(
        e2, WkTf, cwT, nullptr, k2h, edg, bk, cb, NS, D, D);

    // FUSED dots2 + node attention
    dots2_node_fused<<<512, 256, FUS_SMEM_BYTES>>>(q2h, k2h, edg, nodesb, ndh);

    // fused tail: tmph = relu(x@Wc0 + nodes@Wc1 + bc0+bc1 + nodes)
    mma_gemm_tail<<<dim3(2, 512), 256, MMA_SMEM_BYTES>>>(
        xrh, ndh, Wc0h, Wc1h, bc01, nodesb, tmph);

    // out = relu(tmph@Wt + bt) (fp32 final)
    mma_gemm<2><<<dim3(2, 512), 256, MMA_SMEM_BYTES>>>(
        tmph, Wth, out, bt, nullptr, nullptr, nullptr, N_NODES, D, D);
}

// round 16
// speedup vs baseline: 1.0170x; 1.0069x over previous
#include <cuda_runtime.h>
#include <cuda_fp16.h>
#include <math.h>
#include <stdint.h>

#define N_NODES 65536
#define D       256
#define NS      512
#define HID     256
#define KTOP    10
#define EPSC    1e-8f
#define SCALE_C 0.0625f  /* 256^-0.5 */

// ---------------------------------------------------------------------------
// Scratch
// ---------------------------------------------------------------------------
__device__ __half g_xh  [(size_t)N_NODES * D];
__device__ __half g_xrh [(size_t)N_NODES * D];
__device__ __half g_kkh [(size_t)N_NODES * D];
__device__ __half g_q2h [(size_t)N_NODES * D];
__device__ __half g_ndh [(size_t)N_NODES * D];
__device__ __half g_tmph[(size_t)N_NODES * D];
__device__ float  g_vv  [(size_t)N_NODES * D];
__device__ float  g_nodes[(size_t)N_NODES * D];
__device__ float  g_part[(size_t)NS * 512 * 24];

__device__ float  g_e    [NS * D];
__device__ __half g_qh   [NS * D];
__device__ __half g_k2h  [NS * D];
__device__ float  g_e2cat[NS * 2 * D];
__device__ float  g_h1   [NS * HID];
__device__ float  g_e2   [NS * D];
__device__ float  g_edg  [NS * D];

__device__ __half g_Wkvqh[3 * D * D];
__device__ __half g_Wc0h [D * D];
__device__ __half g_Wc1h [D * D];
__device__ __half g_Wth  [D * D];
__device__ float  g_bkvq [3 * D];
__device__ float  g_bc01 [D];
__device__ float  g_WqTf [D * D];
__device__ float  g_WkTf [D * D];
__device__ float  g_Wm1T [HID * 2 * D];
__device__ float  g_Wm2T [D * HID];
__device__ float  g_cwT  [D * D];

// grid-barrier state (zero-initialized; gen is monotone across graph replays,
// cnt is reset by the last arriver each use)
__device__ unsigned g_barcnt[2];
__device__ unsigned g_bargen[2];

// ---------------------------------------------------------------------------
// helpers
// ---------------------------------------------------------------------------
__device__ __forceinline__ void mma16n8k16(float& c0, float& c1, float& c2, float& c3,
                                           uint32_t a0, uint32_t a1, uint32_t a2, uint32_t a3,
                                           uint32_t b0, uint32_t b1) {
    asm volatile(
        "mma.sync.aligned.m16n8k16.row.col.f32.f16.f16.f32 "
        "{%0,%1,%2,%3}, {%4,%5,%6,%7}, {%8,%9}, {%0,%1,%2,%3};"
        : "+f"(c0), "+f"(c1), "+f"(c2), "+f"(c3)
        : "r"(a0), "r"(a1), "r"(a2), "r"(a3), "r"(b0), "r"(b1));
}
__device__ __forceinline__ void ldsm_x4(uint32_t& r0, uint32_t& r1, uint32_t& r2, uint32_t& r3,
                                        uint32_t addr) {
    asm volatile("ldmatrix.sync.aligned.m8n8.x4.shared.b16 {%0,%1,%2,%3}, [%4];"
                 : "=r"(r0), "=r"(r1), "=r"(r2), "=r"(r3) : "r"(addr));
}
__device__ __forceinline__ void cp_async16(void* smem_dst, const void* gmem_src) {
    uint32_t d = (uint32_t)__cvta_generic_to_shared(smem_dst);
    asm volatile("cp.async.cg.shared.global [%0], [%1], 16;" :: "r"(d), "l"(gmem_src));
}
__device__ __forceinline__ void cp_commit() { asm volatile("cp.async.commit_group;"); }
__device__ __forceinline__ void cp_wait2()  { asm volatile("cp.async.wait_group 2;"); }
__device__ __forceinline__ void cp_wait0()  { asm volatile("cp.async.wait_group 0;"); }

__device__ __forceinline__ void grid_barrier(int i, unsigned nctas) {
    __syncthreads();
    if (threadIdx.x == 0) {
        __threadfence();
        unsigned gen = atomicAdd(&g_bargen[i], 0u);
        unsigned old = atomicAdd(&g_barcnt[i], 1u);
        if (old == nctas - 1) {
            g_barcnt[i] = 0;
            __threadfence();
            atomicAdd(&g_bargen[i], 1u);
        } else {
            while (atomicAdd(&g_bargen[i], 0u) == gen) { }
        }
        __threadfence();
    }
    __syncthreads();
}

#define LDH   40
#define HBUF  (128 * LDH)
#define MMA_SMEM_BYTES (6 * HBUF * 2)   /* 3-stage: 3 A + 3 B buffers */

struct FragOff {
    uint32_t a_off[2];
    uint32_t b_off[4];
};
__device__ __forceinline__ FragOff make_frag_off(int wid, int lane) {
    FragOff f;
    int warp_m = wid & 3, warp_n = wid >> 2;
#pragma unroll
    for (int mt = 0; mt < 2; mt++)
        f.a_off[mt] = ((warp_m * 32 + mt * 16 + (lane & 15)) * LDH + (lane >> 4) * 8) * 2;
    int b_row = (lane & 7) + ((lane >> 4) & 1) * 8;
    int b_koff = ((lane >> 3) & 1) * 8;
#pragma unroll
    for (int p = 0; p < 4; p++)
        f.b_off[p] = ((warp_n * 64 + p * 16 + b_row) * LDH + b_koff) * 2;
    return f;
}
#define MMA_COMPUTE_CHUNK(Ab, Bb, fo, acc)                                        \
    _Pragma("unroll")                                                             \
    for (int ks = 0; ks < 32; ks += 16) {                                         \
        uint32_t ra[2][4];                                                        \
        uint32_t rb[4][4];                                                        \
        _Pragma("unroll")                                                         \
        for (int mt = 0; mt < 2; mt++)                                            \
            ldsm_x4(ra[mt][0], ra[mt][1], ra[mt][2], ra[mt][3],                   \
                    (Ab) + (fo).a_off[mt] + ks * 2);                              \
        _Pragma("unroll")                                                         \
        for (int p = 0; p < 4; p++)                                               \
            ldsm_x4(rb[p][0], rb[p][1], rb[p][2], rb[p][3],                       \
                    (Bb) + (fo).b_off[p] + ks * 2);                               \
        _Pragma("unroll")                                                         \
        for (int p = 0; p < 4; p++)                                               \
            _Pragma("unroll")                                                     \
            for (int mt = 0; mt < 2; mt++) {                                      \
                mma16n8k16(acc[mt][2 * p][0], acc[mt][2 * p][1],                  \
                           acc[mt][2 * p][2], acc[mt][2 * p][3],                  \
                           ra[mt][0], ra[mt][1], ra[mt][2], ra[mt][3],            \
                           rb[p][0], rb[p][1]);                                   \
                mma16n8k16(acc[mt][2 * p + 1][0], acc[mt][2 * p + 1][1],          \
                           acc[mt][2 * p + 1][2], acc[mt][2 * p + 1][3],          \
                           ra[mt][0], ra[mt][1], ra[mt][2], ra[mt][3],            \
                           rb[p][2], rb[p][3]);                                   \
            }                                                                     \
    }

// 3-stage pipelined chunk loop (variadic: body may contain commas).
#define PIPE3_LOOP(NCHv, LOADFN, ...)                                             \
    LOADFN(0, 0); cp_commit();                                                    \
    LOADFN(1, 1); cp_commit();                                                    \
    for (int ch = 0; ch < (NCHv); ch++) {                                         \
        if (ch + 2 < (NCHv)) LOADFN(ch + 2, (ch + 2) % 3);                        \
        cp_commit();                                                              \
        cp_wait2();                                                               \
        __syncthreads();                                                          \
        { __VA_ARGS__ }                                                           \
        __syncthreads();                                                          \
    }

// ---------------------------------------------------------------------------
// Pipelined fp16 NT GEMM. EPI: 2 = C=relu(acc+bias) fp32, 4 = kvq split
// ---------------------------------------------------------------------------
template <int EPI>
__global__ void __launch_bounds__(256) mma_gemm(
    const __half* __restrict__ A, const __half* __restrict__ B,
    float* __restrict__ C, const float* __restrict__ bias,
    float* __restrict__ Cf2, __half* __restrict__ Ch, __half* __restrict__ Ch2,
    int M, int Ntot, int K) {
    extern __shared__ __half smh[];
    const int tid = threadIdx.x;
    const int wid = tid >> 5, lane = tid & 31;
    const int warp_m = wid & 3;
    const int warp_n = wid >> 2;
    const int bm = blockIdx.y * 128;
    const int bn = blockIdx.x * 128;
    const int grp = lane >> 2;
    const int tig = lane & 3;
    const uint32_t smb = (uint32_t)__cvta_generic_to_shared(smh);
    FragOff fo = make_frag_off(wid, lane);

    float acc[2][8][4];
#pragma unroll
    for (int i = 0; i < 2; i++)
#pragma unroll
        for (int j = 0; j < 8; j++)
#pragma unroll
            for (int r = 0; r < 4; r++) acc[i][j][r] = 0.f;

    const int NCH = K >> 5;
    auto load_tile = [&](int ch, int buf) {
        const __half* Ag = A + (size_t)bm * K + ch * 32;
        const __half* Bg = B + (size_t)bn * K + ch * 32;
        __half* Ad = smh + buf * HBUF;
        __half* Bd = smh + (3 + buf) * HBUF;
#pragma unroll
        for (int i = 0; i < 2; i++) {
            int id = tid + (i << 8);
            int row = id >> 2, c8 = (id & 3) << 3;
            cp_async16(Ad + row * LDH + c8, Ag + (size_t)row * K + c8);
            cp_async16(Bd + row * LDH + c8, Bg + (size_t)row * K + c8);
        }
    };

    PIPE3_LOOP(NCH, load_tile,
        const uint32_t Ab = smb + (ch % 3) * HBUF * 2;
        const uint32_t Bb = smb + (3 + ch % 3) * HBUF * 2;
        MMA_COMPUTE_CHUNK(Ab, Bb, fo, acc);
    )

#pragma unroll
    for (int mt = 0; mt < 2; mt++) {
        int r0 = bm + warp_m * 32 + mt * 16 + grp;
#pragma unroll
        for (int nt = 0; nt < 8; nt++) {
            int c0 = bn + warp_n * 64 + nt * 8 + 2 * tig;
#pragma unroll
            for (int half_ = 0; half_ < 2; half_++) {
                int rr = r0 + half_ * 8;
                float vx = acc[mt][nt][2 * half_ + 0] + bias[c0];
                float vy = acc[mt][nt][2 * half_ + 1] + bias[c0 + 1];
                if constexpr (EPI == 4) {
                    int seg = c0 >> 8;
                    size_t idx = (size_t)rr * D + (c0 & 255);
                    if (seg == 0) {
                        vx = fmaxf(vx, 0.f); vy = fmaxf(vy, 0.f);
                        *reinterpret_cast<__half2*>(Ch + idx) = __floats2half2_rn(vx, vy);
                    } else if (seg == 1) {
                        vx = fmaxf(vx, 0.f); vy = fmaxf(vy, 0.f);
                        float2 o; o.x = vx; o.y = vy;
                        *reinterpret_cast<float2*>(Cf2 + idx) = o;
                    } else {
                        *reinterpret_cast<__half2*>(Ch2 + idx) = __floats2half2_rn(vx, vy);
                    }
                } else {
                    vx = fmaxf(vx, 0.f); vy = fmaxf(vy, 0.f);
                    size_t idx = (size_t)rr * Ntot + c0;
                    float2 o; o.x = vx; o.y = vy;
                    *reinterpret_cast<float2*>(C + idx) = o;
                }
            }
        }
    }
}

// ---------------------------------------------------------------------------
// Tail fused GEMM: Ch = relu( [A1|A2] @ [B1;B2]^T + bias + aux )  (K=512)
// ---------------------------------------------------------------------------
__global__ void __launch_bounds__(256) mma_gemm_tail(
    const __half* __restrict__ A1, const __half* __restrict__ A2,
    const __half* __restrict__ B1, const __half* __restrict__ B2,
    const float* __restrict__ bias, const float* __restrict__ aux,
    __half* __restrict__ Ch) {
    extern __shared__ __half smh[];
    const int tid = threadIdx.x;
    const int wid = tid >> 5, lane = tid & 31;
    const int warp_m = wid & 3;
    const int warp_n = wid >> 2;
    const int bm = blockIdx.y * 128;
    const int bn = blockIdx.x * 128;
    const int grp = lane >> 2;
    const int tig = lane & 3;
    const int K = D;
    const uint32_t smb = (uint32_t)__cvta_generic_to_shared(smh);
    FragOff fo = make_frag_off(wid, lane);

    float acc[2][8][4];
#pragma unroll
    for (int i = 0; i < 2; i++)
#pragma unroll
        for (int j = 0; j < 8; j++)
#pragma unroll
            for (int r = 0; r < 4; r++) acc[i][j][r] = 0.f;

    auto load_tile = [&](int ch, int buf) {
        const __half* Ag = (ch < 8) ? A1 + (size_t)bm * K + ch * 32
                                    : A2 + (size_t)bm * K + (ch - 8) * 32;
        const __half* Bg = (ch < 8) ? B1 + (size_t)bn * K + ch * 32
                                    : B2 + (size_t)bn * K + (ch - 8) * 32;
        __half* Ad = smh + buf * HBUF;
        __half* Bd = smh + (3 + buf) * HBUF;
#pragma unroll
        for (int i = 0; i < 2; i++) {
            int id = tid + (i << 8);
            int row = id >> 2, c8 = (id & 3) << 3;
            cp_async16(Ad + row * LDH + c8, Ag + (size_t)row * K + c8);
            cp_async16(Bd + row * LDH + c8, Bg + (size_t)row * K + c8);
        }
    };

    PIPE3_LOOP(16, load_tile,
        const uint32_t Ab = smb + (ch % 3) * HBUF * 2;
        const uint32_t Bb = smb + (3 + ch % 3) * HBUF * 2;
        MMA_COMPUTE_CHUNK(Ab, Bb, fo, acc);
    )

#pragma unroll
    for (int mt = 0; mt < 2; mt++) {
        int r0 = bm + warp_m * 32 + mt * 16 + grp;
#pragma unroll
        for (int nt = 0; nt < 8; nt++) {
            int c0 = bn + warp_n * 64 + nt * 8 + 2 * tig;
#pragma unroll
            for (int half_ = 0; half_ < 2; half_++) {
                int rr = r0 + half_ * 8;
                size_t idx = (size_t)rr * D + c0;
                float2 aa = *reinterpret_cast<const float2*>(aux + idx);
                float vx = fmaxf(acc[mt][nt][2 * half_ + 0] + bias[c0] + aa.x, 0.f);
                float vy = fmaxf(acc[mt][nt][2 * half_ + 1] + bias[c0 + 1] + aa.y, 0.f);
                *reinterpret_cast<__half2*>(Ch + idx) = __floats2half2_rn(vx, vy);
            }
        }
    }
}

// ---------------------------------------------------------------------------
// FUSED dots2 + node attention
// ---------------------------------------------------------------------------
#define LGD 133
#define FUS_SMEM_BYTES (128 * LGD * 4 + 128 * KTOP * 4 + 128 * KTOP * 4)

__global__ void __launch_bounds__(256) dots2_node_fused(
    const __half* __restrict__ A, const __half* __restrict__ Bk,
    const float* __restrict__ edg,
    float* __restrict__ nodes, __half* __restrict__ nodesh) {
    extern __shared__ __half smh[];
    float* logits = reinterpret_cast<float*>(smh);
    float* wv_s = logits + 128 * LGD;
    int*   wi_s = reinterpret_cast<int*>(wv_s + 128 * KTOP);

    const int tid = threadIdx.x;
    const int wid = tid >> 5, lane = tid & 31;
    const int warp_m = wid & 3;
    const int warp_n = wid >> 2;
    const int bm = blockIdx.x * 128;
    const int grp = lane >> 2;
    const int tig = lane & 3;
    const int K = D;
    const uint32_t smb = (uint32_t)__cvta_generic_to_shared(smh);
    FragOff fo = make_frag_off(wid, lane);

    float m_run = -INFINITY, z_run = 0.f;
    float tv[KTOP]; int ti[KTOP];
#pragma unroll
    for (int i = 0; i < KTOP; i++) { tv[i] = -INFINITY; ti[i] = 0; }

    for (int sc = 0; sc < 4; sc++) {
        float acc[2][8][4];
#pragma unroll
        for (int i = 0; i < 2; i++)
#pragma unroll
            for (int j = 0; j < 8; j++)
#pragma unroll
                for (int r = 0; r < 4; r++) acc[i][j][r] = 0.f;

        const __half* Bg_base = Bk + (size_t)(sc * 128) * K;
        auto load_tile = [&](int ch, int buf) {
            const __half* Ag = A + (size_t)bm * K + ch * 32;
            const __half* Bg = Bg_base + ch * 32;
            __half* Ad = smh + buf * HBUF;
            __half* Bd = smh + (3 + buf) * HBUF;
#pragma unroll
            for (int i = 0; i < 2; i++) {
                int id = tid + (i << 8);
                int row = id >> 2, c8 = (id & 3) << 3;
                cp_async16(Ad + row * LDH + c8, Ag + (size_t)row * K + c8);
                cp_async16(Bd + row * LDH + c8, Bg + (size_t)row * K + c8);
            }
        };

        PIPE3_LOOP(8, load_tile,
            const uint32_t Ab = smb + (ch % 3) * HBUF * 2;
            const uint32_t Bb = smb + (3 + ch % 3) * HBUF * 2;
            MMA_COMPUTE_CHUNK(Ab, Bb, fo, acc);
        )

#pragma unroll
        for (int mt = 0; mt < 2; mt++) {
            int r0 = warp_m * 32 + mt * 16 + grp;
#pragma unroll
            for (int nt = 0; nt < 8; nt++) {
                int c0 = warp_n * 64 + nt * 8 + 2 * tig;
#pragma unroll
                for (int half_ = 0; half_ < 2; half_++) {
                    int rr = r0 + half_ * 8;
                    logits[rr * LGD + c0]     = acc[mt][nt][2 * half_ + 0] * SCALE_C;
                    logits[rr * LGD + c0 + 1] = acc[mt][nt][2 * half_ + 1] * SCALE_C;
                }
            }
        }
        __syncthreads();
        if (tid < 128) {
            const float* lr = logits + tid * LGD;
            for (int j = 0; j < 128; j++) {
                float v = lr[j];
                if (v > m_run) { z_run *= __expf(m_run - v); m_run = v; }
                z_run += __expf(v - m_run);
                if (v > tv[KTOP - 1]) {
                    int ix = sc * 128 + j;
                    float vt = v;
#pragma unroll
                    for (int p = 0; p < KTOP; p++)
                        if (vt > tv[p]) {
                            float tf = tv[p]; tv[p] = vt; vt = tf;
                            int tt = ti[p]; ti[p] = ix; ix = tt;
                        }
                }
            }
        }
        __syncthreads();
    }
    if (tid < 128) {
        float zin = 1.f / z_run;
#pragma unroll
        for (int i = 0; i < KTOP; i++) {
            wv_s[tid * KTOP + i] = __expf(tv[i] - m_run) * zin;
            wi_s[tid * KTOP + i] = ti[i];
        }
    }
    __syncthreads();
    for (int rr = 0; rr < 16; rr++) {
        int r = wid * 16 + rr;
        float w_[KTOP]; int ix_[KTOP];
#pragma unroll
        for (int i = 0; i < KTOP; i++) { w_[i] = wv_s[r * KTOP + i]; ix_[i] = wi_s[r * KTOP + i]; }
        float* po = nodes + (size_t)(bm + r) * D;
        __half* ph = nodesh + (size_t)(bm + r) * D;
#pragma unroll
        for (int j = 0; j < 8; j++) {
            int c = lane + 32 * j;
            float a2 = 0.f;
#pragma unroll
            for (int i = 0; i < KTOP; i++) a2 += w_[i] * edg[(size_t)ix_[i] * D + c];
            po[c] = a2;
            ph[c] = __float2half_rn(a2);
        }
    }
}

// ---------------------------------------------------------------------------
// dots1 Phase A
// ---------------------------------------------------------------------------
#define FUS1_SMEM_BYTES (128 * LGD * 4)

__global__ void __launch_bounds__(256) dots1_partial(
    const __half* __restrict__ A, const __half* __restrict__ Bk,
    float* __restrict__ part) {
    extern __shared__ __half smh[];
    float* logits = reinterpret_cast<float*>(smh);
    const int tid = threadIdx.x;
    const int wid = tid >> 5, lane = tid & 31;
    const int warp_m = wid & 3;
    const int warp_n = wid >> 2;
    const int bm = blockIdx.y * 128;
    const int bnc = blockIdx.x;
    const int grp = lane >> 2;
    const int tig = lane & 3;
    const int K = D;
    const uint32_t smb = (uint32_t)__cvta_generic_to_shared(smh);
    FragOff fo = make_frag_off(wid, lane);

    float acc[2][8][4];
#pragma unroll
    for (int i = 0; i < 2; i++)
#pragma unroll
        for (int j = 0; j < 8; j++)
#pragma unroll
            for (int r = 0; r < 4; r++) acc[i][j][r] = 0.f;

    const __half* Bg_base = Bk + (size_t)bnc * 128 * K;
    auto load_tile = [&](int ch, int buf) {
        const __half* Ag = A + (size_t)bm * K + ch * 32;
        const __half* Bg = Bg_base + ch * 32;
        __half* Ad = smh + buf * HBUF;
        __half* Bd = smh + (3 + buf) * HBUF;
#pragma unroll
        for (int i = 0; i < 2; i++) {
            int id = tid + (i << 8);
            int row = id >> 2, c8 = (id & 3) << 3;
            cp_async16(Ad + row * LDH + c8, Ag + (size_t)row * K + c8);
            cp_async16(Bd + row * LDH + c8, Bg + (size_t)row * K + c8);
        }
    };

    PIPE3_LOOP(8, load_tile,
        const uint32_t Ab = smb + (ch % 3) * HBUF * 2;
        const uint32_t Bb = smb + (3 + ch % 3) * HBUF * 2;
        MMA_COMPUTE_CHUNK(Ab, Bb, fo, acc);
    )

#pragma unroll
    for (int mt = 0; mt < 2; mt++) {
        int r0 = warp_m * 32 + mt * 16 + grp;
#pragma unroll
        for (int nt = 0; nt < 8; nt++) {
            int c0 = warp_n * 64 + nt * 8 + 2 * tig;
#pragma unroll
            for (int half_ = 0; half_ < 2; half_++) {
                int rr = r0 + half_ * 8;
                logits[rr * LGD + c0]     = acc[mt][nt][2 * half_ + 0] * SCALE_C;
                logits[rr * LGD + c0 + 1] = acc[mt][nt][2 * half_ + 1] * SCALE_C;
            }
        }
    }
    __syncthreads();
    if (tid < 128) {
        const float* lr = logits + tid * LGD;
        float m = -INFINITY, z = 0.f;
        float tv[KTOP]; int ti[KTOP];
#pragma unroll
        for (int i = 0; i < KTOP; i++) { tv[i] = -INFINITY; ti[i] = 0; }
        for (int j = 0; j < 128; j++) {
            float v = lr[j];
            if (v > m) { z *= __expf(m - v); m = v; }
            z += __expf(v - m);
            if (v > tv[KTOP - 1]) {
                int ix = bnc * 128 + j;
                float vt = v;
#pragma unroll
                for (int p = 0; p < KTOP; p++)
                    if (vt > tv[p]) {
                        float tf = tv[p]; tv[p] = vt; vt = tf;
                        int tt = ti[p]; ti[p] = ix; ix = tt;
                    }
            }
        }
        float* rec = part + ((size_t)(bm + tid) * 512 + bnc) * 24;
        rec[0] = m; rec[1] = z;
#pragma unroll
        for (int i = 0; i < KTOP; i++) {
            rec[2 + i] = tv[i];
            rec[12 + i] = __int_as_float(ti[i]);
        }
    }
}

// ---------------------------------------------------------------------------
// dots1 Phase B merge
// ---------------------------------------------------------------------------
__global__ void slot_merge(const float* __restrict__ part, const float* __restrict__ vv,
                           const float* __restrict__ e, float* __restrict__ e2cat) {
    __shared__ float sv[256 * KTOP];
    __shared__ int   si[256 * KTOP];
    __shared__ float sm_m[256];
    __shared__ float sm_z[256];
    __shared__ float sw[KTOP];
    __shared__ int   sx[KTOP];
    int s = blockIdx.x, tid = threadIdx.x;

    const float* r0 = part + ((size_t)s * 512 + 2 * tid) * 24;
    const float* r1 = r0 + 24;
    float m = r0[0], z = r0[1];
    float tv[KTOP]; int ti[KTOP];
#pragma unroll
    for (int i = 0; i < KTOP; i++) { tv[i] = r0[2 + i]; ti[i] = __float_as_int(r0[12 + i]); }
    {
        float mb = r1[0], zb = r1[1];
        float mn = fmaxf(m, mb);
        z = z * __expf(m - mn) + zb * __expf(mb - mn);
        m = mn;
#pragma unroll
        for (int i = 0; i < KTOP; i++) {
            float v = r1[2 + i];
            int ix = __float_as_int(r1[12 + i]);
            if (v > tv[KTOP - 1]) {
#pragma unroll
                for (int p = 0; p < KTOP; p++)
                    if (v > tv[p]) {
                        float tf = tv[p]; tv[p] = v; v = tf;
                        int tt = ti[p]; ti[p] = ix; ix = tt;
                    }
            }
        }
    }
#pragma unroll
    for (int i = 0; i < KTOP; i++) { sv[tid * KTOP + i] = tv[i]; si[tid * KTOP + i] = ti[i]; }
    sm_m[tid] = m; sm_z[tid] = z;
    __syncthreads();
    for (int stride = 128; stride >= 1; stride >>= 1) {
        if (tid < stride) {
#pragma unroll
            for (int i = 0; i < KTOP; i++) { tv[i] = sv[tid * KTOP + i]; ti[i] = si[tid * KTOP + i]; }
#pragma unroll
            for (int i = 0; i < KTOP; i++) {
                float v = sv[(tid + stride) * KTOP + i];
                int ix = si[(tid + stride) * KTOP + i];
                if (v > tv[KTOP - 1]) {
#pragma unroll
                    for (int p = 0; p < KTOP; p++)
                        if (v > tv[p]) {
                            float tf = tv[p]; tv[p] = v; v = tf;
                            int tt = ti[p]; ti[p] = ix; ix = tt;
                        }
                }
            }
#pragma unroll
            for (int i = 0; i < KTOP; i++) { sv[tid * KTOP + i] = tv[i]; si[tid * KTOP + i] = ti[i]; }
            float ma = sm_m[tid], za = sm_z[tid];
            float mb = sm_m[tid + stride], zb = sm_z[tid + stride];
            float mn = fmaxf(ma, mb);
            float zn = za * __expf(ma - mn) + zb * __expf(mb - mn);
            sm_m[tid] = mn; sm_z[tid] = zn;
        }
        __syncthreads();
    }
    float maxv = sm_m[0];
    float Z = sm_z[0];
    if (tid < KTOP) {
        float p = __expf(sv[tid] - maxv) / Z;
        sw[tid] = (p + EPSC) / (1.f + (float)N_NODES * EPSC);
        sx[tid] = si[tid];
    }
    __syncthreads();
    float acc = 0.f;
#pragma unroll
    for (int i = 0; i < KTOP; i++) acc += sw[i] * vv[(size_t)sx[i] * D + tid];
    e2cat[(size_t)s * 2 * D + D + tid] = acc;
    e2cat[(size_t)s * 2 * D + tid] = e[(size_t)s * D + tid];
}

// ---------------------------------------------------------------------------
// prep: weight transposes + bias tasks + edges LN. grid (64, 14), block (32,8)
// ---------------------------------------------------------------------------
__device__ __forceinline__ void tr_tile(const float* in, float* outF, __half* outH,
                                        int R, int C, int bx, float (*tile)[33]) {
    int tx = threadIdx.x, tyw = threadIdx.y;
    int xt = bx & (C / 32 - 1), yt = bx / (C / 32);
    int bxc = xt * 32, byr = yt * 32;
    for (int y = tyw; y < 32; y += 8)
        tile[y][tx] = in[(size_t)(byr + y) * C + bxc + tx];
    __syncthreads();
    if (outH) {
        for (int y = tyw; y < 32; y += 8)
            outH[(size_t)(bxc + y) * R + byr + tx] = __float2half_rn(tile[tx][y]);
    } else {
        for (int y = tyw; y < 32; y += 8)
            outF[(size_t)(bxc + y) * R + byr + tx] = tile[tx][y];
    }
}

__global__ void prep(
    const float* Wk, const float* Wv, const float* Wq, const float* Wc0,
    const float* Wc1, const float* Wt, const float* cw, const float* Wm1,
    const float* Wm2,
    __half* Wkvqh, __half* Wc0h, __half* Wc1h, __half* Wth,
    float* WqTf, float* WkTf, float* cwT, float* Wm1T, float* Wm2T,
    const float* bk, const float* bv, const float* bq, float* bkvq,
    const float* bc0, const float* bc1, float* bc01,
    const float* noise, const float* emu, const float* elog,
    const float* lew, const float* leb, float* e) {
    __shared__ float tile[32][33];
    int task = blockIdx.y, bx = blockIdx.x;
    switch (task) {
    case 0: tr_tile(Wk,  nullptr, Wkvqh,             D, D, bx, tile); break;
    case 1: tr_tile(Wv,  nullptr, Wkvqh + D * D,     D, D, bx, tile); break;
    case 2: tr_tile(Wq,  nullptr, Wkvqh + 2 * D * D, D, D, bx, tile); break;
    case 3: tr_tile(Wc0, nullptr, Wc0h, D, D, bx, tile); break;
    case 4: tr_tile(Wc1, nullptr, Wc1h, D, D, bx, tile); break;
    case 5: tr_tile(Wt,  nullptr, Wth,  D, D, bx, tile); break;
    case 6: tr_tile(Wq,  WqTf, nullptr, D, D, bx, tile); break;
    case 7: tr_tile(Wk,  WkTf, nullptr, D, D, bx, tile); break;
    case 8: tr_tile(cw,  cwT,  nullptr, D, D, bx, tile); break;
    case 9: tr_tile(Wm2, Wm2T, nullptr, HID, D, bx, tile); break;
    case 10: tr_tile(Wm1, Wm1T, nullptr, 2 * D, HID, bx, tile); break;
    case 11: tr_tile(Wm1, Wm1T, nullptr, 2 * D, HID, bx + 64, tile); break;
    case 12: {
        if (bx == 0) {
            int i = threadIdx.y * 32 + threadIdx.x;
            bkvq[i] = bk[i]; bkvq[D + i] = bv[i]; bkvq[2 * D + i] = bq[i];
            bc01[i] = bc0[i] + bc1[i];
        }
        break;
    }
    default: {  // 13: edges LN
        int warp = bx * 8 + threadIdx.y;
        int lane = threadIdx.x;
        const float* r = noise + (size_t)warp * D;
        float v[8]; float s = 0.f;
#pragma unroll
        for (int j = 0; j < 8; j++) {
            int c = lane + 32 * j;
            v[j] = emu[c] + expf(elog[c]) * r[c];
            s += v[j];
        }
#pragma unroll
        for (int st = 16; st; st >>= 1) s += __shfl_xor_sync(0xffffffffu, s, st);
        float mu = s * (1.f / 256.f);
        float q = 0.f;
#pragma unroll
        for (int j = 0; j < 8; j++) { float d2 = v[j] - mu; q += d2 * d2; }
#pragma unroll
        for (int st = 16; st; st >>= 1) q += __shfl_xor_sync(0xffffffffu, q, st);
        float rinv = rsqrtf(q * (1.f / 256.f) + 1e-5f);
        float* po = e + (size_t)warp * D;
#pragma unroll
        for (int j = 0; j < 8; j++) {
            int c = lane + 32 * j;
            po[c] = (v[j] - mu) * rinv * lew[c] + leb[c];
        }
        break;
    }
    }
}

// ---------------------------------------------------------------------------
// LayerNorm -> half + x->half copy
// ---------------------------------------------------------------------------
__global__ void ln_rows(const float* __restrict__ x, const float* __restrict__ w,
                        const float* __restrict__ b, __half* __restrict__ o,
                        __half* __restrict__ xrh, int M) {
    int warp = (blockIdx.x * blockDim.x + threadIdx.x) >> 5;
    int lane = threadIdx.x & 31;
    if (warp >= M) return;
    const float* r = x + (size_t)warp * D;
    float v[8]; float s = 0.f;
#pragma unroll
    for (int j = 0; j < 8; j++) { v[j] = r[lane + 32 * j]; s += v[j]; }
#pragma unroll
    for (int st = 16; st; st >>= 1) s += __shfl_xor_sync(0xffffffffu, s, st);
    float mu = s * (1.f / 256.f);
    float q = 0.f;
#pragma unroll
    for (int j = 0; j < 8; j++) { float d = v[j] - mu; q += d * d; }
#pragma unroll
    for (int st = 16; st; st >>= 1) q += __shfl_xor_sync(0xffffffffu, q, st);
    float rinv = rsqrtf(q * (1.f / 256.f) + 1e-5f);
    __half* po = o + (size_t)warp * D;
    __half* px = xrh + (size_t)warp * D;
#pragma unroll
    for (int j = 0; j < 8; j++) {
        int c = lane + 32 * j;
        po[c] = __float2half_rn((v[j] - mu) * rinv * w[c] + b[c]);
        px[c] = __float2half_rn(v[j]);
    }
}

// ---------------------------------------------------------------------------
// Small fp32 NT GEMM phase (32x32 tile, 128 threads) as device function.
// ---------------------------------------------------------------------------
#define GSW 260
#define GS_SMEM_BYTES  (2 * 32 * GSW * 4)
#define GS_SMEM_BYTES3 (3 * 32 * GSW * 4)

template <bool RELU, bool OUTH, bool DUAL>
__device__ __forceinline__ void gs_phase(
    float* gs, const float* A, const float* B, const float* B2d,
    float* C, __half* Ch, float* C2,
    const float* bias, const float* bias2, int N, int K) {
    float* As = gs;
    float* Bs = gs + 32 * GSW;
    float* B2s = gs + 2 * 32 * GSW;
    const int tid = threadIdx.x;
    const int tx = tid & 7, ty = tid >> 3;
    const int bm = blockIdx.y * 32, bn = blockIdx.x * 32;

    float acc[2][4], acc2[2][4];
#pragma unroll
    for (int i = 0; i < 2; i++)
#pragma unroll
        for (int j = 0; j < 4; j++) { acc[i][j] = 0.f; acc2[i][j] = 0.f; }

    for (int k0 = 0; k0 < K; k0 += 256) {
#pragma unroll
        for (int i = 0; i < 16; i++) {
            int id = tid + i * 128;
            int row = id >> 6, c4 = (id & 63) << 2;
            cp_async16(&As[row * GSW + c4], &A[(size_t)(bm + row) * K + k0 + c4]);
            cp_async16(&Bs[row * GSW + c4], &B[(size_t)(bn + row) * K + k0 + c4]);
            if (DUAL)
                cp_async16(&B2s[row * GSW + c4], &B2d[(size_t)(bn + row) * K + k0 + c4]);
        }
        cp_commit();
        cp_wait0();
        __syncthreads();
#pragma unroll 4
        for (int k = 0; k < 256; k += 4) {
            float4 a0 = *reinterpret_cast<const float4*>(&As[(ty * 2 + 0) * GSW + k]);
            float4 a1 = *reinterpret_cast<const float4*>(&As[(ty * 2 + 1) * GSW + k]);
#pragma unroll
            for (int j = 0; j < 4; j++) {
                float4 b4 = *reinterpret_cast<const float4*>(&Bs[(tx + 8 * j) * GSW + k]);
                acc[0][j] += a0.x * b4.x + a0.y * b4.y + a0.z * b4.z + a0.w * b4.w;
                acc[1][j] += a1.x * b4.x + a1.y * b4.y + a1.z * b4.z + a1.w * b4.w;
                if (DUAL) {
                    float4 c4v = *reinterpret_cast<const float4*>(&B2s[(tx + 8 * j) * GSW + k]);
                    acc2[0][j] += a0.x * c4v.x + a0.y * c4v.y + a0.z * c4v.z + a0.w * c4v.w;
                    acc2[1][j] += a1.x * c4v.x + a1.y * c4v.y + a1.z * c4v.z + a1.w * c4v.w;
                }
            }
        }
        __syncthreads();
    }
#pragma unroll
    for (int i = 0; i < 2; i++) {
        int m = bm + ty * 2 + i;
#pragma unroll
        for (int j = 0; j < 4; j++) {
            int n = bn + tx + 8 * j;
            float v = acc[i][j] + bias[n];
            if (RELU) v = fmaxf(v, 0.f);
            if (OUTH) Ch[(size_t)m * N + n] = __float2half_rn(v);
            else      C [(size_t)m * N + n] = v;
            if (DUAL) {
                float v2 = acc2[i][j] + bias2[n];
                C2[(size_t)m * N + n] = v2;
            }
        }
    }
}

// Standalone single-pass small GEMM (used for q projection)
__global__ void __launch_bounds__(128) gemm_small_q(
    const float* __restrict__ A, const float* __restrict__ B,
    __half* __restrict__ Ch, const float* __restrict__ bias, int N, int K) {
    extern __shared__ float gs[];
    gs_phase<true, true, false>(gs, A, B, nullptr, nullptr, Ch, nullptr,
                                bias, nullptr, N, K);
}

// Persistent fused slot MLP: e2cat -> h1 -> e2 -> {k2h, edg} with grid barriers.
// grid (8,16) = 128 CTAs (all resident on 148 SMs), block 128.
__global__ void __launch_bounds__(128) slot_mlp_fused(
    const float* __restrict__ e2cat,
    const float* __restrict__ Wm1T, const float* __restrict__ bm1,
    float* __restrict__ h1,
    const float* __restrict__ Wm2T, const float* __restrict__ bm2,
    float* __restrict__ e2,
    const float* __restrict__ WkTf, const float* __restrict__ cwT,
    const float* __restrict__ bk, const float* __restrict__ cb,
    __half* __restrict__ k2h, float* __restrict__ edg) {
    extern __shared__ float gs[];
    const unsigned NCTAS = 128;
    // phase 1: h1 = relu(e2cat @ Wm1 + bm1)   (K=512)
    gs_phase<true, false, false>(gs, e2cat, Wm1T, nullptr, h1, nullptr, nullptr,
                                 bm1, nullptr, HID, 2 * D);
    grid_barrier(0, NCTAS);
    // phase 2: e2 = h1 @ Wm2 + bm2            (K=256)
    gs_phase<false, false, false>(gs, h1, Wm2T, nullptr, e2, nullptr, nullptr,
                                  bm2, nullptr, D, HID);
    grid_barrier(1, NCTAS);
    // phase 3: k2 = relu(e2@Wk+bk) -> half; edg = e2@cw+cb -> float (dual)
    gs_phase<true, true, true>(gs, e2, WkTf, cwT, nullptr, k2h, edg,
                               bk, cb, D, D);
}

// ---------------------------------------------------------------------------
// Launch
// ---------------------------------------------------------------------------
extern "C" void kernel_launch(void* const* d_in, const int* in_sizes, int n_in,
                              void* d_out, int out_size) {
    (void)in_sizes; (void)n_in; (void)out_size;
    const float* x      = (const float*)d_in[0];
    const float* enoise = (const float*)d_in[1];
    const float* emu    = (const float*)d_in[2];
    const float* elog   = (const float*)d_in[3];
    const float* lnw    = (const float*)d_in[4];
    const float* lnb    = (const float*)d_in[5];
    const float* lew    = (const float*)d_in[6];
    const float* leb    = (const float*)d_in[7];
    const float* Wq = (const float*)d_in[8];  const float* bq = (const float*)d_in[9];
    const float* Wk = (const float*)d_in[10]; const float* bk = (const float*)d_in[11];
    const float* Wv = (const float*)d_in[12]; const float* bv = (const float*)d_in[13];
    const float* Wm1 = (const float*)d_in[14]; const float* bm1 = (const float*)d_in[15];
    const float* Wm2 = (const float*)d_in[16]; const float* bm2 = (const float*)d_in[17];
    const float* cw = (const float*)d_in[18];  const float* cb = (const float*)d_in[19];
    const float* Wc0 = (const float*)d_in[20]; const float* bc0 = (const float*)d_in[21];
    const float* Wc1 = (const float*)d_in[22]; const float* bc1 = (const float*)d_in[23];
    const float* Wt = (const float*)d_in[24];  const float* bt = (const float*)d_in[25];
    float* out = (float*)d_out;

    void* p;
    cudaGetSymbolAddress(&p, g_xh);    __half* xh = (__half*)p;
    cudaGetSymbolAddress(&p, g_xrh);   __half* xrh = (__half*)p;
    cudaGetSymbolAddress(&p, g_kkh);   __half* kkh = (__half*)p;
    cudaGetSymbolAddress(&p, g_q2h);   __half* q2h = (__half*)p;
    cudaGetSymbolAddress(&p, g_ndh);   __half* ndh = (__half*)p;
    cudaGetSymbolAddress(&p, g_tmph);  __half* tmph = (__half*)p;
    cudaGetSymbolAddress(&p, g_vv);    float* vvb = (float*)p;
    cudaGetSymbolAddress(&p, g_nodes); float* nodesb = (float*)p;
    cudaGetSymbolAddress(&p, g_part);  float* part = (float*)p;
    cudaGetSymbolAddress(&p, g_e);     float* e = (float*)p;
    cudaGetSymbolAddress(&p, g_qh);    __half* qh = (__half*)p;
    cudaGetSymbolAddress(&p, g_k2h);   __half* k2h = (__half*)p;
    cudaGetSymbolAddress(&p, g_e2cat); float* e2cat = (float*)p;
    cudaGetSymbolAddress(&p, g_h1);    float* h1 = (float*)p;
    cudaGetSymbolAddress(&p, g_e2);    float* e2 = (float*)p;
    cudaGetSymbolAddress(&p, g_edg);   float* edg = (float*)p;
    cudaGetSymbolAddress(&p, g_Wkvqh); __half* Wkvqh = (__half*)p;
    cudaGetSymbolAddress(&p, g_Wc0h);  __half* Wc0h = (__half*)p;
    cudaGetSymbolAddress(&p, g_Wc1h);  __half* Wc1h = (__half*)p;
    cudaGetSymbolAddress(&p, g_Wth);   __half* Wth = (__half*)p;
    cudaGetSymbolAddress(&p, g_bkvq);  float* bkvq = (float*)p;
    cudaGetSymbolAddress(&p, g_bc01);  float* bc01 = (float*)p;
    cudaGetSymbolAddress(&p, g_WqTf);  float* WqTf = (float*)p;
    cudaGetSymbolAddress(&p, g_WkTf);  float* WkTf = (float*)p;
    cudaGetSymbolAddress(&p, g_Wm1T);  float* Wm1T = (float*)p;
    cudaGetSymbolAddress(&p, g_Wm2T);  float* Wm2T = (float*)p;
    cudaGetSymbolAddress(&p, g_cwT);   float* cwT = (float*)p;

    cudaFuncSetAttribute(mma_gemm<2>, cudaFuncAttributeMaxDynamicSharedMemorySize, MMA_SMEM_BYTES);
    cudaFuncSetAttribute(mma_gemm<4>, cudaFuncAttributeMaxDynamicSharedMemorySize, MMA_SMEM_BYTES);
    cudaFuncSetAttribute(mma_gemm_tail, cudaFuncAttributeMaxDynamicSharedMemorySize, MMA_SMEM_BYTES);
    cudaFuncSetAttribute(dots2_node_fused, cudaFuncAttributeMaxDynamicSharedMemorySize, FUS_SMEM_BYTES);
    cudaFuncSetAttribute(dots1_partial, cudaFuncAttributeMaxDynamicSharedMemorySize, FUS1_SMEM_BYTES);
    cudaFuncSetAttribute(gemm_small_q, cudaFuncAttributeMaxDynamicSharedMemorySize, GS_SMEM_BYTES3);
    cudaFuncSetAttribute(slot_mlp_fused, cudaFuncAttributeMaxDynamicSharedMemorySize, GS_SMEM_BYTES3);

    prep<<<dim3(64, 14), dim3(32, 8)>>>(
        Wk, Wv, Wq, Wc0, Wc1, Wt, cw, Wm1, Wm2,
        Wkvqh, Wc0h, Wc1h, Wth, WqTf, WkTf, cwT, Wm1T, Wm2T,
        bk, bv, bq, bkvq, bc0, bc1, bc01,
        enoise, emu, elog, lew, leb, e);

    ln_rows<<<N_NODES / 8, 256>>>(x, lnw, lnb, xh, xrh, N_NODES);

    // fused: kk(half,relu), vv(fp32,relu), q2(half)
    mma_gemm<4><<<dim3(6, 512), 256, MMA_SMEM_BYTES>>>(
        xh, Wkvqh, nullptr, bkvq, vvb, kkh, q2h, N_NODES, 3 * D, D);

    // q = relu(e@Wq+bq) -> half
    gemm_small_q<<<dim3(8, 16), 128, GS_SMEM_BYTES3>>>(e, WqTf, qh, bq, D, D);

    // dots1 partials + merge
    dots1_partial<<<dim3(512, 4), 256, FUS1_SMEM_BYTES>>>(qh, kkh, part);
    slot_merge<<<NS, 256>>>(part, vvb, e, e2cat);

    // FUSED slot MLP chain (persistent, grid barriers between phases)
    slot_mlp_fused<<<dim3(8, 16), 128, GS_SMEM_BYTES3>>>(
        e2cat, Wm1T, bm1, h1, Wm2T, bm2, e2, WkTf, cwT, bk, cb, k2h, edg);

    // FUSED dots2 + node attention
    dots2_node_fused<<<512, 256, FUS_SMEM_BYTES>>>(q2h, k2h, edg, nodesb, ndh);

    // fused tail: tmph = relu(x@Wc0 + nodes@Wc1 + bc0+bc1 + nodes)
    mma_gemm_tail<<<dim3(2, 512), 256, MMA_SMEM_BYTES>>>(
        xrh, ndh, Wc0h, Wc1h, bc01, nodesb, tmph);

    // out = relu(tmph@Wt + bt) (fp32 final)
    mma_gemm<2><<<dim3(2, 512), 256, MMA_SMEM_BYTES>>>(
        tmph, Wth, out, bt, nullptr, nullptr, nullptr, N_NODES, D, D);
}